// round 1
// baseline (speedup 1.0000x reference)
#include <cuda_runtime.h>
#include <cuda_bf16.h>

// Problem constants
#define T_LEN 1024
#define B_SZ  64
#define D_SZ  512
#define H_SZ  512
#define BH    (B_SZ * H_SZ)          // 32768
#define TBH   (T_LEN * BH)           // 33554432

// Scratch (static device globals; allocation-free per harness rules)
__device__ float g_Wc[D_SZ * D_SZ];      // fused fc->layer0 weight: Wc[h,e] = sum_d w0[h,d]*fc_w[d,e]
__device__ float g_bc[D_SZ];             // fused bias: bc[h] = w0[h,:]·fc_b + b0[h]
__device__ float g_bufA[TBH];            // pre0, later pre1
__device__ float g_bufB[TBH];            // out0

// ---------------------------------------------------------------------------
// Kernel 1: Wc = w0 @ fc_w   (512x512x512, NN layout)  — tiny, simple tiles
// ---------------------------------------------------------------------------
__global__ void fuse_weights_kernel(const float* __restrict__ w0,
                                    const float* __restrict__ fc_w) {
    __shared__ float As[16][16];
    __shared__ float Bs[16][16];
    int tx = threadIdx.x, ty = threadIdx.y;
    int h = blockIdx.y * 16 + ty;
    int e = blockIdx.x * 16 + tx;
    float acc = 0.f;
    for (int d0 = 0; d0 < D_SZ; d0 += 16) {
        As[ty][tx] = w0[h * D_SZ + d0 + tx];
        Bs[ty][tx] = fc_w[(d0 + ty) * D_SZ + e];
        __syncthreads();
#pragma unroll
        for (int k = 0; k < 16; k++)
            acc = fmaf(As[ty][k], Bs[k][tx], acc);
        __syncthreads();
    }
    g_Wc[h * D_SZ + e] = acc;
}

// ---------------------------------------------------------------------------
// Kernel 2: bc[h] = dot(w0[h,:], fc_b) + b0[h]
// ---------------------------------------------------------------------------
__global__ void fuse_bias_kernel(const float* __restrict__ w0,
                                 const float* __restrict__ fc_b,
                                 const float* __restrict__ b0) {
    int h = blockIdx.x * blockDim.x + threadIdx.x;
    if (h >= H_SZ) return;
    float acc = b0[h];
    const float* row = w0 + h * D_SZ;
#pragma unroll 8
    for (int d = 0; d < D_SZ; d++)
        acc = fmaf(row[d], fc_b[d], acc);
    g_bc[h] = acc;
}

// ---------------------------------------------------------------------------
// Kernel 3: C[M,512] = A[M,512] @ B[512,512]^T + bias   (A,B both K-major)
//   128x128 block tile, BK=16, 256 threads, 8x8 per-thread micro-tile.
// ---------------------------------------------------------------------------
#define BM 128
#define BN 128
#define BK 16
#define SSTR 132   // padded smem row stride (floats), 16B-aligned, kills conflicts

__global__ __launch_bounds__(256, 2)
void sgemm_nt_kernel(const float* __restrict__ A,
                     const float* __restrict__ B,
                     const float* __restrict__ bias,
                     float* __restrict__ C) {
    __shared__ float As[BK * SSTR];
    __shared__ float Bs[BK * SSTR];

    const int tid  = threadIdx.x;
    const int ldRow = tid >> 2;            // 0..63
    const int ldCol = (tid & 3) * 4;       // k offset: 0,4,8,12
    const int tRow = tid >> 4;             // 0..15
    const int tCol = tid & 15;             // 0..15

    const float* Ap = A + (size_t)blockIdx.x * BM * D_SZ;
    const float* Bp = B + (size_t)blockIdx.y * BN * D_SZ;

    float acc[8][8];
#pragma unroll
    for (int i = 0; i < 8; i++)
#pragma unroll
        for (int j = 0; j < 8; j++) acc[i][j] = 0.f;

    for (int k0 = 0; k0 < D_SZ; k0 += BK) {
        // load A tile (transpose into As[k][m]) and B tile (into Bs[k][n])
#pragma unroll
        for (int r = 0; r < 2; r++) {
            int row = ldRow + r * 64;
            float4 va = *(const float4*)(Ap + row * D_SZ + k0 + ldCol);
            As[(ldCol + 0) * SSTR + row] = va.x;
            As[(ldCol + 1) * SSTR + row] = va.y;
            As[(ldCol + 2) * SSTR + row] = va.z;
            As[(ldCol + 3) * SSTR + row] = va.w;
            float4 vb = *(const float4*)(Bp + row * D_SZ + k0 + ldCol);
            Bs[(ldCol + 0) * SSTR + row] = vb.x;
            Bs[(ldCol + 1) * SSTR + row] = vb.y;
            Bs[(ldCol + 2) * SSTR + row] = vb.z;
            Bs[(ldCol + 3) * SSTR + row] = vb.w;
        }
        __syncthreads();

#pragma unroll
        for (int kk = 0; kk < BK; kk++) {
            float ra[8], rb[8];
            float4 a0 = *(const float4*)(&As[kk * SSTR + tRow * 8 + 0]);
            float4 a1 = *(const float4*)(&As[kk * SSTR + tRow * 8 + 4]);
            float4 b0v = *(const float4*)(&Bs[kk * SSTR + tCol * 8 + 0]);
            float4 b1v = *(const float4*)(&Bs[kk * SSTR + tCol * 8 + 4]);
            ra[0]=a0.x; ra[1]=a0.y; ra[2]=a0.z; ra[3]=a0.w;
            ra[4]=a1.x; ra[5]=a1.y; ra[6]=a1.z; ra[7]=a1.w;
            rb[0]=b0v.x; rb[1]=b0v.y; rb[2]=b0v.z; rb[3]=b0v.w;
            rb[4]=b1v.x; rb[5]=b1v.y; rb[6]=b1v.z; rb[7]=b1v.w;
#pragma unroll
            for (int i = 0; i < 8; i++)
#pragma unroll
                for (int j = 0; j < 8; j++)
                    acc[i][j] = fmaf(ra[i], rb[j], acc[i][j]);
        }
        __syncthreads();
    }

    // epilogue: add bias, store
    const int nBase = blockIdx.y * BN + tCol * 8;
    float4 bia0 = *(const float4*)(bias + nBase + 0);
    float4 bia1 = *(const float4*)(bias + nBase + 4);
#pragma unroll
    for (int i = 0; i < 8; i++) {
        int m = blockIdx.x * BM + tRow * 8 + i;
        float* Crow = C + (size_t)m * H_SZ + nBase;
        float4 o0, o1;
        o0.x = acc[i][0] + bia0.x; o0.y = acc[i][1] + bia0.y;
        o0.z = acc[i][2] + bia0.z; o0.w = acc[i][3] + bia0.w;
        o1.x = acc[i][4] + bia1.x; o1.y = acc[i][5] + bia1.y;
        o1.z = acc[i][6] + bia1.z; o1.w = acc[i][7] + bia1.w;
        *(float4*)(Crow + 0) = o0;
        *(float4*)(Crow + 4) = o1;
    }
}

// ---------------------------------------------------------------------------
// Kernel 4: IndRNN recurrence.  32768 independent serial chains over T=1024.
//   h_t = relu(pre[t] + u*h_{t-1});  8-deep load prefetch for MLP.
// ---------------------------------------------------------------------------
__global__ __launch_bounds__(256)
void indrnn_rec_kernel(const float* __restrict__ pre,
                       float* __restrict__ out,
                       const float* __restrict__ h_init,
                       const float* __restrict__ u,
                       float* __restrict__ h_final) {
    const int idx = blockIdx.x * blockDim.x + threadIdx.x;   // b*H + h
    const float uu = u[idx & (H_SZ - 1)];
    float h = h_init[idx];

    float p[8];
#pragma unroll
    for (int j = 0; j < 8; j++)
        p[j] = pre[(size_t)j * BH + idx];

    for (int t = 0; t < T_LEN; t += 8) {
#pragma unroll
        for (int j = 0; j < 8; j++) {
            float cur = p[j];
            int tn = t + 8 + j;
            if (tn < T_LEN) p[j] = pre[(size_t)tn * BH + idx];
            h = fmaxf(fmaf(uu, h, cur), 0.f);
            out[(size_t)(t + j) * BH + idx] = h;
        }
    }
    h_final[idx] = h;
}

// ---------------------------------------------------------------------------
// Launch
//   inputs: x, hidden, fc_w, fc_b, w0, b0, u0, w1, b1, u1
//   output: [ out1 (T*B*H) | hn (2*B*H) ]
// ---------------------------------------------------------------------------
extern "C" void kernel_launch(void* const* d_in, const int* in_sizes, int n_in,
                              void* d_out, int out_size) {
    const float* x      = (const float*)d_in[0];
    const float* hidden = (const float*)d_in[1];
    const float* fc_w   = (const float*)d_in[2];
    const float* fc_b   = (const float*)d_in[3];
    const float* w0     = (const float*)d_in[4];
    const float* b0     = (const float*)d_in[5];
    const float* u0     = (const float*)d_in[6];
    const float* w1     = (const float*)d_in[7];
    const float* b1     = (const float*)d_in[8];
    const float* u1     = (const float*)d_in[9];
    float* out = (float*)d_out;

    float *bufA, *bufB, *Wc, *bc;
    cudaGetSymbolAddress((void**)&bufA, g_bufA);
    cudaGetSymbolAddress((void**)&bufB, g_bufB);
    cudaGetSymbolAddress((void**)&Wc, g_Wc);
    cudaGetSymbolAddress((void**)&bc, g_bc);

    // 1) fuse fc into layer-0 weights
    fuse_weights_kernel<<<dim3(D_SZ / 16, D_SZ / 16), dim3(16, 16)>>>(w0, fc_w);
    fuse_bias_kernel<<<2, 256>>>(w0, fc_b, b0);

    // 2) pre0 = x @ Wc^T + bc
    sgemm_nt_kernel<<<dim3(T_LEN * B_SZ / BM, H_SZ / BN), 256>>>(x, Wc, bc, bufA);

    // 3) layer-0 recurrence: out0 -> bufB, h0_final -> d_out[TBH ..]
    indrnn_rec_kernel<<<BH / 256, 256>>>(bufA, bufB, hidden, u0, out + TBH);

    // 4) pre1 = out0 @ w1^T + b1
    sgemm_nt_kernel<<<dim3(T_LEN * B_SZ / BM, H_SZ / BN), 256>>>(bufB, w1, b1, bufA);

    // 5) layer-1 recurrence: out1 -> d_out[0..], h1_final -> d_out[TBH+BH ..]
    indrnn_rec_kernel<<<BH / 256, 256>>>(bufA, out, hidden + BH, u1, out + TBH + BH);
}

// round 3
// speedup vs baseline: 1.4357x; 1.4357x over previous
#include <cuda_runtime.h>
#include <cuda_bf16.h>
#include <cstdint>

// Problem constants
#define T_LEN 1024
#define B_SZ  64
#define D_SZ  512
#define H_SZ  512
#define BH    (B_SZ * H_SZ)          // 32768
#define TBH   (T_LEN * BH)           // 33554432

// ---------------------------------------------------------------------------
// Scratch (static device globals; allocation-free per harness rules)
// ---------------------------------------------------------------------------
__device__ float          g_Wc[D_SZ * D_SZ];
__device__ float          g_bc[D_SZ];
__device__ __nv_bfloat16  g_Wch[D_SZ * D_SZ];
__device__ __nv_bfloat16  g_Wcl[D_SZ * D_SZ];
__device__ __nv_bfloat16  g_w1h[D_SZ * D_SZ];
__device__ __nv_bfloat16  g_w1l[D_SZ * D_SZ];
__device__ __nv_bfloat16  g_xh[TBH];
__device__ __nv_bfloat16  g_xl[TBH];
__device__ __nv_bfloat16  g_o0h[TBH];
__device__ __nv_bfloat16  g_o0l[TBH];
__device__ float          g_pre[TBH];

// ---------------------------------------------------------------------------
// sm_80-compatible PTX helpers (cp.async / ldmatrix / mma.sync only — no
// tcgen05: the harness targets base sm_103, which lacks the 'a' feature set)
// ---------------------------------------------------------------------------
__device__ __forceinline__ uint32_t smem_u32(const void* p) {
    uint32_t a;
    asm("{ .reg .u64 t; cvta.to.shared.u64 t, %1; cvt.u32.u64 %0, t; }"
        : "=r"(a) : "l"(p));
    return a;
}

__device__ __forceinline__ void cp_async16(uint32_t dst, const void* src) {
    asm volatile("cp.async.cg.shared.global [%0], [%1], 16;"
                 :: "r"(dst), "l"(src));
}
__device__ __forceinline__ void cp_commit() {
    asm volatile("cp.async.commit_group;");
}
__device__ __forceinline__ void cp_wait1() {
    asm volatile("cp.async.wait_group 1;");
}
__device__ __forceinline__ void cp_wait0() {
    asm volatile("cp.async.wait_group 0;");
}

__device__ __forceinline__ void ldsm_x4(uint32_t& r0, uint32_t& r1,
                                        uint32_t& r2, uint32_t& r3,
                                        uint32_t addr) {
    asm volatile("ldmatrix.sync.aligned.m8n8.x4.shared.b16 {%0,%1,%2,%3}, [%4];"
                 : "=r"(r0), "=r"(r1), "=r"(r2), "=r"(r3) : "r"(addr));
}

__device__ __forceinline__ void mma_bf16(float* d, const uint32_t* a,
                                         const uint32_t* b) {
    asm volatile(
        "mma.sync.aligned.m16n8k16.row.col.f32.bf16.bf16.f32 "
        "{%0,%1,%2,%3}, {%4,%5,%6,%7}, {%8,%9}, {%0,%1,%2,%3};"
        : "+f"(d[0]), "+f"(d[1]), "+f"(d[2]), "+f"(d[3])
        : "r"(a[0]), "r"(a[1]), "r"(a[2]), "r"(a[3]), "r"(b[0]), "r"(b[1]));
}

// ---------------------------------------------------------------------------
// Kernel 1: Wc = w0 @ fc_w (512^3 fp32, small)
// ---------------------------------------------------------------------------
__global__ void fuse_weights_kernel(const float* __restrict__ w0,
                                    const float* __restrict__ fc_w) {
    __shared__ float As[16][16];
    __shared__ float Bs[16][16];
    int tx = threadIdx.x, ty = threadIdx.y;
    int h = blockIdx.y * 16 + ty;
    int e = blockIdx.x * 16 + tx;
    float acc = 0.f;
    for (int d0 = 0; d0 < D_SZ; d0 += 16) {
        As[ty][tx] = w0[h * D_SZ + d0 + tx];
        Bs[ty][tx] = fc_w[(d0 + ty) * D_SZ + e];
        __syncthreads();
#pragma unroll
        for (int k = 0; k < 16; k++)
            acc = fmaf(As[ty][k], Bs[k][tx], acc);
        __syncthreads();
    }
    g_Wc[h * D_SZ + e] = acc;
}

// ---------------------------------------------------------------------------
// Kernel 2: bc[h] = dot(w0[h,:], fc_b) + b0[h]
// ---------------------------------------------------------------------------
__global__ void fuse_bias_kernel(const float* __restrict__ w0,
                                 const float* __restrict__ fc_b,
                                 const float* __restrict__ b0) {
    int h = blockIdx.x * blockDim.x + threadIdx.x;
    if (h >= H_SZ) return;
    float acc = b0[h];
    const float* row = w0 + h * D_SZ;
#pragma unroll 8
    for (int d = 0; d < D_SZ; d++)
        acc = fmaf(row[d], fc_b[d], acc);
    g_bc[h] = acc;
}

// ---------------------------------------------------------------------------
// Kernel 3: fp32 -> (hi, lo) bf16 split (vectorized x4)
// ---------------------------------------------------------------------------
__global__ __launch_bounds__(256)
void split_kernel(const float* __restrict__ src,
                  __nv_bfloat16* __restrict__ hi,
                  __nv_bfloat16* __restrict__ lo, int n4) {
    int i = blockIdx.x * blockDim.x + threadIdx.x;
    if (i >= n4) return;
    float4 v = ((const float4*)src)[i];
    __nv_bfloat16 h0 = __float2bfloat16(v.x);
    __nv_bfloat16 h1 = __float2bfloat16(v.y);
    __nv_bfloat16 h2 = __float2bfloat16(v.z);
    __nv_bfloat16 h3 = __float2bfloat16(v.w);
    __nv_bfloat162 hh0; hh0.x = h0; hh0.y = h1;
    __nv_bfloat162 hh1; hh1.x = h2; hh1.y = h3;
    __nv_bfloat162 ll0, ll1;
    ll0.x = __float2bfloat16(v.x - __bfloat162float(h0));
    ll0.y = __float2bfloat16(v.y - __bfloat162float(h1));
    ll1.x = __float2bfloat16(v.z - __bfloat162float(h2));
    ll1.y = __float2bfloat16(v.w - __bfloat162float(h3));
    ((__nv_bfloat162*)hi)[i * 2 + 0] = hh0;
    ((__nv_bfloat162*)hi)[i * 2 + 1] = hh1;
    ((__nv_bfloat162*)lo)[i * 2 + 0] = ll0;
    ((__nv_bfloat162*)lo)[i * 2 + 1] = ll1;
}

// ---------------------------------------------------------------------------
// Kernel 4: HMMA (mma.sync bf16) split GEMM.
//   C[M,512] = Ah@Bh^T + Ah@Bl^T + Al@Bh^T + bias, K'=1536 concat sweep.
//   CTA 128x128, BK=32, 8 warps (4Mx2N), warp tile 32x64, 3-stage cp.async.
// ---------------------------------------------------------------------------
#define ROW_B   80                    // padded smem row stride (bytes)
#define TILE_B  (128 * ROW_B)         // 10240 bytes per operand tile
#define STAGE_B (2 * TILE_B)          // A + B per stage = 20480
#define NSTAGES 3
#define GSMEM   (NSTAGES * STAGE_B)   // 61440

__global__ __launch_bounds__(256, 1)
void gemm_hmma_kernel(const __nv_bfloat16* __restrict__ Ah,
                      const __nv_bfloat16* __restrict__ Al,
                      const __nv_bfloat16* __restrict__ Bh,
                      const __nv_bfloat16* __restrict__ Bl,
                      const float* __restrict__ bias,
                      float* __restrict__ C) {
    extern __shared__ __align__(128) char smem[];
    const uint32_t sb = smem_u32(smem);
    const int tid = threadIdx.x;
    const int lane = tid & 31;
    const int wid = tid >> 5;
    const int wm = wid & 3;            // 0..3  (M direction, 32 rows each)
    const int wn = wid >> 2;           // 0..1  (N direction, 64 cols each)

    const size_t mBase = (size_t)blockIdx.x * 128;
    const size_t nBase = (size_t)blockIdx.y * 128;

    float acc[2][8][4];
#pragma unroll
    for (int i = 0; i < 2; i++)
#pragma unroll
        for (int j = 0; j < 8; j++)
#pragma unroll
            for (int k = 0; k < 4; k++) acc[i][j][k] = 0.f;

    // copy indices: this thread moves chunks {tid, tid+256} of A and of B
    const int r0c = tid >> 2, c0c = tid & 3;          // chunk tid
    const int r1c = (tid + 256) >> 2, c1c = tid & 3;  // chunk tid+256

    auto issue = [&](int s) {
        const __nv_bfloat16 *As, *Bs;
        int koff;
        if (s < 16)      { As = Ah; Bs = Bh; koff = s * 32; }
        else if (s < 32) { As = Ah; Bs = Bl; koff = (s - 16) * 32; }
        else             { As = Al; Bs = Bh; koff = (s - 32) * 32; }
        const uint32_t stA = sb + (s % NSTAGES) * STAGE_B;
        const uint32_t stB = stA + TILE_B;
        cp_async16(stA + r0c * ROW_B + c0c * 16,
                   As + (mBase + r0c) * 512 + koff + c0c * 8);
        cp_async16(stA + r1c * ROW_B + c1c * 16,
                   As + (mBase + r1c) * 512 + koff + c1c * 8);
        cp_async16(stB + r0c * ROW_B + c0c * 16,
                   Bs + (nBase + r0c) * 512 + koff + c0c * 8);
        cp_async16(stB + r1c * ROW_B + c1c * 16,
                   Bs + (nBase + r1c) * 512 + koff + c1c * 8);
        cp_commit();
    };

    issue(0);
    issue(1);

    // ldmatrix lane addressing (constant offsets per thread)
    const int a_lr = lane & 15;         // row within 16-row tile
    const int a_kc = lane >> 4;         // 0/1 -> k chunk (+16B)
    const int b_g  = lane >> 3;         // 0..3
    const int b_nr = (b_g >> 1) * 8 + (lane & 7);  // n row within 16
    const int b_kc = b_g & 1;           // k chunk

    for (int s = 0; s < 48; s++) {
        cp_wait1();
        __syncthreads();
        if (s + 2 < 48) issue(s + 2);

        const uint32_t stA = sb + (s % NSTAGES) * STAGE_B;
        const uint32_t stB = stA + TILE_B;

#pragma unroll
        for (int kk = 0; kk < 2; kk++) {           // two k16 steps
            uint32_t af[2][4];
#pragma unroll
            for (int mi = 0; mi < 2; mi++) {
                uint32_t addr = stA + (wm * 32 + mi * 16 + a_lr) * ROW_B
                              + kk * 32 + a_kc * 16;
                ldsm_x4(af[mi][0], af[mi][1], af[mi][2], af[mi][3], addr);
            }
#pragma unroll
            for (int nj = 0; nj < 4; nj++) {       // 16 n-cols per ldmatrix
                uint32_t b0, b1, b2, b3;
                uint32_t addr = stB + (wn * 64 + nj * 16 + b_nr) * ROW_B
                              + kk * 32 + b_kc * 16;
                ldsm_x4(b0, b1, b2, b3, addr);
                uint32_t bf0[2] = {b0, b1};
                uint32_t bf1[2] = {b2, b3};
#pragma unroll
                for (int mi = 0; mi < 2; mi++) {
                    mma_bf16(acc[mi][nj * 2 + 0], af[mi], bf0);
                    mma_bf16(acc[mi][nj * 2 + 1], af[mi], bf1);
                }
            }
        }
        __syncthreads();
    }
    cp_wait0();

    // Epilogue: bias + store (2 m-tiles x 8 n-subtiles, float2 per row)
    const int rr = lane >> 2;
    const int cc = (lane & 3) * 2;
#pragma unroll
    for (int mi = 0; mi < 2; mi++) {
        const size_t row0 = mBase + wm * 32 + mi * 16 + rr;
#pragma unroll
        for (int ns = 0; ns < 8; ns++) {
            const size_t col = nBase + wn * 64 + ns * 8 + cc;
            const float2 bv = *(const float2*)(bias + col);
            float2 v0, v1;
            v0.x = acc[mi][ns][0] + bv.x;
            v0.y = acc[mi][ns][1] + bv.y;
            v1.x = acc[mi][ns][2] + bv.x;
            v1.y = acc[mi][ns][3] + bv.y;
            *(float2*)(C + row0 * 512 + col) = v0;
            *(float2*)(C + (row0 + 8) * 512 + col) = v1;
        }
    }
}

// ---------------------------------------------------------------------------
// Kernel 5a: IndRNN recurrence, fp32 out (layer 1 -> d_out)
// ---------------------------------------------------------------------------
#define REC_P 16
__global__ __launch_bounds__(128)
void rec_f32_kernel(const float* __restrict__ pre,
                    float* __restrict__ out,
                    const float* __restrict__ h_init,
                    const float* __restrict__ u,
                    float* __restrict__ h_final) {
    const int idx = blockIdx.x * 128 + threadIdx.x;
    const float uu = u[idx & (H_SZ - 1)];
    float h = h_init[idx];
    float p[REC_P];
#pragma unroll
    for (int j = 0; j < REC_P; j++)
        p[j] = pre[(size_t)j * BH + idx];
    for (int t = 0; t < T_LEN; t += REC_P) {
#pragma unroll
        for (int j = 0; j < REC_P; j++) {
            float cur = p[j];
            int tn = t + REC_P + j;
            if (tn < T_LEN) p[j] = pre[(size_t)tn * BH + idx];
            h = fmaxf(fmaf(uu, h, cur), 0.f);
            out[(size_t)(t + j) * BH + idx] = h;
        }
    }
    h_final[idx] = h;
}

// ---------------------------------------------------------------------------
// Kernel 5b: IndRNN recurrence, writes bf16 (hi, lo) split (layer 0 -> GEMM2)
// ---------------------------------------------------------------------------
__global__ __launch_bounds__(128)
void rec_bf16_kernel(const float* __restrict__ pre,
                     __nv_bfloat16* __restrict__ oh,
                     __nv_bfloat16* __restrict__ ol,
                     const float* __restrict__ h_init,
                     const float* __restrict__ u,
                     float* __restrict__ h_final) {
    const int idx = blockIdx.x * 128 + threadIdx.x;
    const float uu = u[idx & (H_SZ - 1)];
    float h = h_init[idx];
    float p[REC_P];
#pragma unroll
    for (int j = 0; j < REC_P; j++)
        p[j] = pre[(size_t)j * BH + idx];
    for (int t = 0; t < T_LEN; t += REC_P) {
#pragma unroll
        for (int j = 0; j < REC_P; j++) {
            float cur = p[j];
            int tn = t + REC_P + j;
            if (tn < T_LEN) p[j] = pre[(size_t)tn * BH + idx];
            h = fmaxf(fmaf(uu, h, cur), 0.f);
            __nv_bfloat16 hh = __float2bfloat16(h);
            oh[(size_t)(t + j) * BH + idx] = hh;
            ol[(size_t)(t + j) * BH + idx] = __float2bfloat16(h - __bfloat162float(hh));
        }
    }
    h_final[idx] = h;
}

// ---------------------------------------------------------------------------
// Launch
//   inputs: x, hidden, fc_w, fc_b, w0, b0, u0, w1, b1, u1
//   output: [ out1 (T*B*H) | hn (2*B*H) ]
// ---------------------------------------------------------------------------
extern "C" void kernel_launch(void* const* d_in, const int* in_sizes, int n_in,
                              void* d_out, int out_size) {
    const float* x      = (const float*)d_in[0];
    const float* hidden = (const float*)d_in[1];
    const float* fc_w   = (const float*)d_in[2];
    const float* fc_b   = (const float*)d_in[3];
    const float* w0     = (const float*)d_in[4];
    const float* b0     = (const float*)d_in[5];
    const float* u0     = (const float*)d_in[6];
    const float* w1     = (const float*)d_in[7];
    const float* b1     = (const float*)d_in[8];
    const float* u1     = (const float*)d_in[9];
    float* out = (float*)d_out;

    float *Wc, *bc, *pre;
    __nv_bfloat16 *Wch, *Wcl, *w1h, *w1l, *xh, *xl, *o0h, *o0l;
    cudaGetSymbolAddress((void**)&Wc,  g_Wc);
    cudaGetSymbolAddress((void**)&bc,  g_bc);
    cudaGetSymbolAddress((void**)&pre, g_pre);
    cudaGetSymbolAddress((void**)&Wch, g_Wch);
    cudaGetSymbolAddress((void**)&Wcl, g_Wcl);
    cudaGetSymbolAddress((void**)&w1h, g_w1h);
    cudaGetSymbolAddress((void**)&w1l, g_w1l);
    cudaGetSymbolAddress((void**)&xh,  g_xh);
    cudaGetSymbolAddress((void**)&xl,  g_xl);
    cudaGetSymbolAddress((void**)&o0h, g_o0h);
    cudaGetSymbolAddress((void**)&o0l, g_o0l);

    cudaFuncSetAttribute(gemm_hmma_kernel,
                         cudaFuncAttributeMaxDynamicSharedMemorySize, GSMEM);

    // 1) fuse fc into layer-0 weights (fp32), then split weights to bf16 pairs
    fuse_weights_kernel<<<dim3(D_SZ / 16, D_SZ / 16), dim3(16, 16)>>>(w0, fc_w);
    fuse_bias_kernel<<<2, 256>>>(w0, fc_b, b0);
    split_kernel<<<(D_SZ * D_SZ / 4 + 255) / 256, 256>>>(Wc, Wch, Wcl, D_SZ * D_SZ / 4);
    split_kernel<<<(D_SZ * D_SZ / 4 + 255) / 256, 256>>>(w1, w1h, w1l, D_SZ * D_SZ / 4);

    // 2) split x to bf16 pairs
    split_kernel<<<(TBH / 4 + 255) / 256, 256>>>(x, xh, xl, TBH / 4);

    // 3) pre0 = x @ Wc^T + bc
    gemm_hmma_kernel<<<dim3(T_LEN * B_SZ / 128, 4), 256, GSMEM>>>(xh, xl, Wch, Wcl, bc, pre);

    // 4) layer-0 recurrence -> bf16 split out0, h0_final
    rec_bf16_kernel<<<BH / 128, 128>>>(pre, o0h, o0l, hidden, u0, out + TBH);

    // 5) pre1 = out0 @ w1^T + b1
    gemm_hmma_kernel<<<dim3(T_LEN * B_SZ / 128, 4), 256, GSMEM>>>(o0h, o0l, w1h, w1l, b1, pre);

    // 6) layer-1 recurrence -> d_out, h1_final
    rec_f32_kernel<<<BH / 128, 128>>>(pre, out, hidden + BH, u1, out + TBH + BH);
}

// round 4
// speedup vs baseline: 1.5772x; 1.0986x over previous
#include <cuda_runtime.h>
#include <cuda_bf16.h>
#include <cstdint>

// Problem constants
#define T_LEN 1024
#define B_SZ  64
#define D_SZ  512
#define H_SZ  512
#define BH    (B_SZ * H_SZ)          // 32768
#define TBH   (T_LEN * BH)           // 33554432

// ---------------------------------------------------------------------------
// Scratch (static device globals; allocation-free per harness rules)
// ---------------------------------------------------------------------------
__device__ float          g_Wc[D_SZ * D_SZ];
__device__ float          g_bc[D_SZ];
__device__ __nv_bfloat16  g_Wch[D_SZ * D_SZ];
__device__ __nv_bfloat16  g_Wcl[D_SZ * D_SZ];
__device__ __nv_bfloat16  g_w1h[D_SZ * D_SZ];
__device__ __nv_bfloat16  g_w1l[D_SZ * D_SZ];
__device__ __nv_bfloat16  g_xh[TBH];
__device__ __nv_bfloat16  g_xl[TBH];
__device__ __nv_bfloat16  g_o0h[TBH];
__device__ __nv_bfloat16  g_o0l[TBH];
__device__ float          g_pre[TBH];

// ---------------------------------------------------------------------------
// sm_80-compatible PTX helpers (cp.async / ldmatrix / mma.sync — base sm_103)
// ---------------------------------------------------------------------------
__device__ __forceinline__ uint32_t smem_u32(const void* p) {
    uint32_t a;
    asm("{ .reg .u64 t; cvta.to.shared.u64 t, %1; cvt.u32.u64 %0, t; }"
        : "=r"(a) : "l"(p));
    return a;
}

__device__ __forceinline__ void cp_async16(uint32_t dst, const void* src) {
    asm volatile("cp.async.cg.shared.global [%0], [%1], 16;"
                 :: "r"(dst), "l"(src));
}
__device__ __forceinline__ void cp_commit() {
    asm volatile("cp.async.commit_group;");
}
__device__ __forceinline__ void cp_wait2() {
    asm volatile("cp.async.wait_group 2;");
}
__device__ __forceinline__ void cp_wait0() {
    asm volatile("cp.async.wait_group 0;");
}

__device__ __forceinline__ void ldsm_x4(uint32_t& r0, uint32_t& r1,
                                        uint32_t& r2, uint32_t& r3,
                                        uint32_t addr) {
    asm volatile("ldmatrix.sync.aligned.m8n8.x4.shared.b16 {%0,%1,%2,%3}, [%4];"
                 : "=r"(r0), "=r"(r1), "=r"(r2), "=r"(r3) : "r"(addr));
}

__device__ __forceinline__ void mma_bf16(float* d, const uint32_t* a,
                                         const uint32_t* b) {
    asm volatile(
        "mma.sync.aligned.m16n8k16.row.col.f32.bf16.bf16.f32 "
        "{%0,%1,%2,%3}, {%4,%5,%6,%7}, {%8,%9}, {%0,%1,%2,%3};"
        : "+f"(d[0]), "+f"(d[1]), "+f"(d[2]), "+f"(d[3])
        : "r"(a[0]), "r"(a[1]), "r"(a[2]), "r"(a[3]), "r"(b[0]), "r"(b[1]));
}

// ---------------------------------------------------------------------------
// Kernel 1: Wc = w0 @ fc_w (512^3 fp32, small)
// ---------------------------------------------------------------------------
__global__ void fuse_weights_kernel(const float* __restrict__ w0,
                                    const float* __restrict__ fc_w) {
    __shared__ float As[16][16];
    __shared__ float Bs[16][16];
    int tx = threadIdx.x, ty = threadIdx.y;
    int h = blockIdx.y * 16 + ty;
    int e = blockIdx.x * 16 + tx;
    float acc = 0.f;
    for (int d0 = 0; d0 < D_SZ; d0 += 16) {
        As[ty][tx] = w0[h * D_SZ + d0 + tx];
        Bs[ty][tx] = fc_w[(d0 + ty) * D_SZ + e];
        __syncthreads();
#pragma unroll
        for (int k = 0; k < 16; k++)
            acc = fmaf(As[ty][k], Bs[k][tx], acc);
        __syncthreads();
    }
    g_Wc[h * D_SZ + e] = acc;
}

// ---------------------------------------------------------------------------
// Kernel 2: bc[h] = dot(w0[h,:], fc_b) + b0[h]
// ---------------------------------------------------------------------------
__global__ void fuse_bias_kernel(const float* __restrict__ w0,
                                 const float* __restrict__ fc_b,
                                 const float* __restrict__ b0) {
    int h = blockIdx.x * blockDim.x + threadIdx.x;
    if (h >= H_SZ) return;
    float acc = b0[h];
    const float* row = w0 + h * D_SZ;
#pragma unroll 8
    for (int d = 0; d < D_SZ; d++)
        acc = fmaf(row[d], fc_b[d], acc);
    g_bc[h] = acc;
}

// ---------------------------------------------------------------------------
// Kernel 3: fp32 -> (hi, lo) bf16 split (vectorized x4)
// ---------------------------------------------------------------------------
__global__ __launch_bounds__(256)
void split_kernel(const float* __restrict__ src,
                  __nv_bfloat16* __restrict__ hi,
                  __nv_bfloat16* __restrict__ lo, int n4) {
    int i = blockIdx.x * blockDim.x + threadIdx.x;
    if (i >= n4) return;
    float4 v = ((const float4*)src)[i];
    __nv_bfloat16 h0 = __float2bfloat16(v.x);
    __nv_bfloat16 h1 = __float2bfloat16(v.y);
    __nv_bfloat16 h2 = __float2bfloat16(v.z);
    __nv_bfloat16 h3 = __float2bfloat16(v.w);
    __nv_bfloat162 hh0; hh0.x = h0; hh0.y = h1;
    __nv_bfloat162 hh1; hh1.x = h2; hh1.y = h3;
    __nv_bfloat162 ll0, ll1;
    ll0.x = __float2bfloat16(v.x - __bfloat162float(h0));
    ll0.y = __float2bfloat16(v.y - __bfloat162float(h1));
    ll1.x = __float2bfloat16(v.z - __bfloat162float(h2));
    ll1.y = __float2bfloat16(v.w - __bfloat162float(h3));
    ((__nv_bfloat162*)hi)[i * 2 + 0] = hh0;
    ((__nv_bfloat162*)hi)[i * 2 + 1] = hh1;
    ((__nv_bfloat162*)lo)[i * 2 + 0] = ll0;
    ((__nv_bfloat162*)lo)[i * 2 + 1] = ll1;
}

// ---------------------------------------------------------------------------
// Kernel 4: HMMA (mma.sync bf16) split GEMM.
//   C[M,512] = Ah@Bh^T + Ah@Bl^T + Al@Bh^T + bias, K'=1536 concat sweep.
//   CTA 128x128, BK=32, 8 warps (4Mx2N), 4-stage cp.async, 1 sync/stage.
//   1-D grid, N-index fastest: 4 consecutive CTAs share one A tile (L2 reuse).
// ---------------------------------------------------------------------------
#define ROW_B   80                    // padded smem row stride (bytes)
#define TILE_B  (128 * ROW_B)         // 10240 bytes per operand tile
#define STAGE_B (2 * TILE_B)          // A + B per stage = 20480
#define NSTAGES 4
#define GSMEM   (NSTAGES * STAGE_B)   // 81920

__global__ __launch_bounds__(256, 1)
void gemm_hmma_kernel(const __nv_bfloat16* __restrict__ Ah,
                      const __nv_bfloat16* __restrict__ Al,
                      const __nv_bfloat16* __restrict__ Bh,
                      const __nv_bfloat16* __restrict__ Bl,
                      const float* __restrict__ bias,
                      float* __restrict__ C) {
    extern __shared__ __align__(128) char smem[];
    const uint32_t sb = smem_u32(smem);
    const int tid = threadIdx.x;
    const int lane = tid & 31;
    const int wid = tid >> 5;
    const int wm = wid & 3;            // 0..3  (M direction, 32 rows each)
    const int wn = wid >> 2;           // 0..1  (N direction, 64 cols each)

    // N fastest so blocks sharing an A tile are adjacent in launch order
    const size_t mBase = (size_t)(blockIdx.x >> 2) * 128;
    const size_t nBase = (size_t)(blockIdx.x & 3) * 128;

    float acc[2][8][4];
#pragma unroll
    for (int i = 0; i < 2; i++)
#pragma unroll
        for (int j = 0; j < 8; j++)
#pragma unroll
            for (int k = 0; k < 4; k++) acc[i][j][k] = 0.f;

    // copy indices: this thread moves chunks {tid, tid+256} of A and of B
    const int r0c = tid >> 2, c0c = tid & 3;          // chunk tid
    const int r1c = (tid + 256) >> 2;                 // chunk tid+256

    auto issue = [&](int s) {
        const __nv_bfloat16 *As, *Bs;
        int koff;
        if (s < 16)      { As = Ah; Bs = Bh; koff = s * 32; }
        else if (s < 32) { As = Ah; Bs = Bl; koff = (s - 16) * 32; }
        else             { As = Al; Bs = Bh; koff = (s - 32) * 32; }
        const uint32_t stA = sb + (s % NSTAGES) * STAGE_B;
        const uint32_t stB = stA + TILE_B;
        cp_async16(stA + r0c * ROW_B + c0c * 16,
                   As + (mBase + r0c) * 512 + koff + c0c * 8);
        cp_async16(stA + r1c * ROW_B + c0c * 16,
                   As + (mBase + r1c) * 512 + koff + c0c * 8);
        cp_async16(stB + r0c * ROW_B + c0c * 16,
                   Bs + (nBase + r0c) * 512 + koff + c0c * 8);
        cp_async16(stB + r1c * ROW_B + c0c * 16,
                   Bs + (nBase + r1c) * 512 + koff + c0c * 8);
        cp_commit();
    };

    issue(0);
    issue(1);
    issue(2);

    // ldmatrix lane addressing (constant offsets per thread)
    const int a_lr = lane & 15;         // row within 16-row tile
    const int a_kc = lane >> 4;         // 0/1 -> k chunk (+16B)
    const int b_g  = lane >> 3;         // 0..3
    const int b_nr = (b_g >> 1) * 8 + (lane & 7);  // n row within 16
    const int b_kc = b_g & 1;           // k chunk

    for (int s = 0; s < 48; s++) {
        cp_wait2();
        __syncthreads();               // all warps done with stage s-1 buffer
        if (s + 3 < 48) issue(s + 3);

        const uint32_t stA = sb + (s % NSTAGES) * STAGE_B;
        const uint32_t stB = stA + TILE_B;

#pragma unroll
        for (int kk = 0; kk < 2; kk++) {           // two k16 steps
            uint32_t af[2][4];
#pragma unroll
            for (int mi = 0; mi < 2; mi++) {
                uint32_t addr = stA + (wm * 32 + mi * 16 + a_lr) * ROW_B
                              + kk * 32 + a_kc * 16;
                ldsm_x4(af[mi][0], af[mi][1], af[mi][2], af[mi][3], addr);
            }
#pragma unroll
            for (int nj = 0; nj < 4; nj++) {       // 16 n-cols per ldmatrix
                uint32_t b0, b1, b2, b3;
                uint32_t addr = stB + (wn * 64 + nj * 16 + b_nr) * ROW_B
                              + kk * 32 + b_kc * 16;
                ldsm_x4(b0, b1, b2, b3, addr);
                uint32_t bf0[2] = {b0, b1};
                uint32_t bf1[2] = {b2, b3};
#pragma unroll
                for (int mi = 0; mi < 2; mi++) {
                    mma_bf16(acc[mi][nj * 2 + 0], af[mi], bf0);
                    mma_bf16(acc[mi][nj * 2 + 1], af[mi], bf1);
                }
            }
        }
    }
    cp_wait0();

    // Epilogue: bias + store (2 m-tiles x 8 n-subtiles, float2 per row)
    const int rr = lane >> 2;
    const int cc = (lane & 3) * 2;
#pragma unroll
    for (int mi = 0; mi < 2; mi++) {
        const size_t row0 = mBase + wm * 32 + mi * 16 + rr;
#pragma unroll
        for (int ns = 0; ns < 8; ns++) {
            const size_t col = nBase + wn * 64 + ns * 8 + cc;
            const float2 bv = *(const float2*)(bias + col);
            float2 v0, v1;
            v0.x = acc[mi][ns][0] + bv.x;
            v0.y = acc[mi][ns][1] + bv.y;
            v1.x = acc[mi][ns][2] + bv.x;
            v1.y = acc[mi][ns][3] + bv.y;
            *(float2*)(C + row0 * 512 + col) = v0;
            *(float2*)(C + (row0 + 8) * 512 + col) = v1;
        }
    }
}

// ---------------------------------------------------------------------------
// Kernel 5a: IndRNN recurrence, fp32 out (layer 1 -> d_out).  P=32 prefetch.
// ---------------------------------------------------------------------------
#define REC_P 32
__global__ __launch_bounds__(128)
void rec_f32_kernel(const float* __restrict__ pre,
                    float* __restrict__ out,
                    const float* __restrict__ h_init,
                    const float* __restrict__ u,
                    float* __restrict__ h_final) {
    const int idx = blockIdx.x * 128 + threadIdx.x;
    const float uu = u[idx & (H_SZ - 1)];
    float h = h_init[idx];
    float p[REC_P];
#pragma unroll
    for (int j = 0; j < REC_P; j++)
        p[j] = pre[(size_t)j * BH + idx];
    for (int t = 0; t < T_LEN; t += REC_P) {
#pragma unroll
        for (int j = 0; j < REC_P; j++) {
            float cur = p[j];
            int tn = t + REC_P + j;
            if (tn < T_LEN) p[j] = pre[(size_t)tn * BH + idx];
            h = fmaxf(fmaf(uu, h, cur), 0.f);
            out[(size_t)(t + j) * BH + idx] = h;
        }
    }
    h_final[idx] = h;
}

// ---------------------------------------------------------------------------
// Kernel 5b: IndRNN recurrence, writes bf16 (hi, lo) split (layer 0 -> GEMM2)
// ---------------------------------------------------------------------------
__global__ __launch_bounds__(128)
void rec_bf16_kernel(const float* __restrict__ pre,
                     __nv_bfloat16* __restrict__ oh,
                     __nv_bfloat16* __restrict__ ol,
                     const float* __restrict__ h_init,
                     const float* __restrict__ u,
                     float* __restrict__ h_final) {
    const int idx = blockIdx.x * 128 + threadIdx.x;
    const float uu = u[idx & (H_SZ - 1)];
    float h = h_init[idx];
    float p[REC_P];
#pragma unroll
    for (int j = 0; j < REC_P; j++)
        p[j] = pre[(size_t)j * BH + idx];
    for (int t = 0; t < T_LEN; t += REC_P) {
#pragma unroll
        for (int j = 0; j < REC_P; j++) {
            float cur = p[j];
            int tn = t + REC_P + j;
            if (tn < T_LEN) p[j] = pre[(size_t)tn * BH + idx];
            h = fmaxf(fmaf(uu, h, cur), 0.f);
            __nv_bfloat16 hh = __float2bfloat16(h);
            oh[(size_t)(t + j) * BH + idx] = hh;
            ol[(size_t)(t + j) * BH + idx] = __float2bfloat16(h - __bfloat162float(hh));
        }
    }
    h_final[idx] = h;
}

// ---------------------------------------------------------------------------
// Launch
//   inputs: x, hidden, fc_w, fc_b, w0, b0, u0, w1, b1, u1
//   output: [ out1 (T*B*H) | hn (2*B*H) ]
// ---------------------------------------------------------------------------
extern "C" void kernel_launch(void* const* d_in, const int* in_sizes, int n_in,
                              void* d_out, int out_size) {
    const float* x      = (const float*)d_in[0];
    const float* hidden = (const float*)d_in[1];
    const float* fc_w   = (const float*)d_in[2];
    const float* fc_b   = (const float*)d_in[3];
    const float* w0     = (const float*)d_in[4];
    const float* b0     = (const float*)d_in[5];
    const float* u0     = (const float*)d_in[6];
    const float* w1     = (const float*)d_in[7];
    const float* b1     = (const float*)d_in[8];
    const float* u1     = (const float*)d_in[9];
    float* out = (float*)d_out;

    float *Wc, *bc, *pre;
    __nv_bfloat16 *Wch, *Wcl, *w1h, *w1l, *xh, *xl, *o0h, *o0l;
    cudaGetSymbolAddress((void**)&Wc,  g_Wc);
    cudaGetSymbolAddress((void**)&bc,  g_bc);
    cudaGetSymbolAddress((void**)&pre, g_pre);
    cudaGetSymbolAddress((void**)&Wch, g_Wch);
    cudaGetSymbolAddress((void**)&Wcl, g_Wcl);
    cudaGetSymbolAddress((void**)&w1h, g_w1h);
    cudaGetSymbolAddress((void**)&w1l, g_w1l);
    cudaGetSymbolAddress((void**)&xh,  g_xh);
    cudaGetSymbolAddress((void**)&xl,  g_xl);
    cudaGetSymbolAddress((void**)&o0h, g_o0h);
    cudaGetSymbolAddress((void**)&o0l, g_o0l);

    cudaFuncSetAttribute(gemm_hmma_kernel,
                         cudaFuncAttributeMaxDynamicSharedMemorySize, GSMEM);

    // 1) fuse fc into layer-0 weights (fp32), then split weights to bf16 pairs
    fuse_weights_kernel<<<dim3(D_SZ / 16, D_SZ / 16), dim3(16, 16)>>>(w0, fc_w);
    fuse_bias_kernel<<<2, 256>>>(w0, fc_b, b0);
    split_kernel<<<(D_SZ * D_SZ / 4 + 255) / 256, 256>>>(Wc, Wch, Wcl, D_SZ * D_SZ / 4);
    split_kernel<<<(D_SZ * D_SZ / 4 + 255) / 256, 256>>>(w1, w1h, w1l, D_SZ * D_SZ / 4);

    // 2) split x to bf16 pairs
    split_kernel<<<(TBH / 4 + 255) / 256, 256>>>(x, xh, xl, TBH / 4);

    // 3) pre0 = x @ Wc^T + bc
    gemm_hmma_kernel<<<T_LEN * B_SZ / 128 * 4, 256, GSMEM>>>(xh, xl, Wch, Wcl, bc, pre);

    // 4) layer-0 recurrence -> bf16 split out0, h0_final
    rec_bf16_kernel<<<BH / 128, 128>>>(pre, o0h, o0l, hidden, u0, out + TBH);

    // 5) pre1 = out0 @ w1^T + b1
    gemm_hmma_kernel<<<T_LEN * B_SZ / 128 * 4, 256, GSMEM>>>(o0h, o0l, w1h, w1l, b1, pre);

    // 6) layer-1 recurrence -> d_out, h1_final
    rec_f32_kernel<<<BH / 128, 128>>>(pre, out, hidden + BH, u1, out + TBH + BH);
}

// round 5
// speedup vs baseline: 2.0244x; 1.2836x over previous
#include <cuda_runtime.h>
#include <cuda_bf16.h>
#include <cstdint>

// Problem constants
#define T_LEN 1024
#define B_SZ  64
#define D_SZ  512
#define H_SZ  512
#define BH    (B_SZ * H_SZ)          // 32768
#define TBH   (T_LEN * BH)           // 33554432

// ---------------------------------------------------------------------------
// Scratch (static device globals; allocation-free per harness rules)
// ---------------------------------------------------------------------------
__device__ float          g_Wc[D_SZ * D_SZ];
__device__ float          g_bc[D_SZ];
__device__ __nv_bfloat16  g_Wch[D_SZ * D_SZ];
__device__ __nv_bfloat16  g_Wcl[D_SZ * D_SZ];
__device__ __nv_bfloat16  g_w1h[D_SZ * D_SZ];
__device__ __nv_bfloat16  g_w1l[D_SZ * D_SZ];
__device__ __nv_bfloat16  g_xh[TBH];
__device__ __nv_bfloat16  g_xl[TBH];
__device__ __nv_bfloat16  g_o0h[TBH];
__device__ __nv_bfloat16  g_o0l[TBH];
__device__ float          g_pre[TBH];

// ---------------------------------------------------------------------------
// sm_80-compatible PTX helpers (cp.async / ldmatrix / mma.sync — base sm_103)
// ---------------------------------------------------------------------------
__device__ __forceinline__ uint32_t smem_u32(const void* p) {
    uint32_t a;
    asm("{ .reg .u64 t; cvta.to.shared.u64 t, %1; cvt.u32.u64 %0, t; }"
        : "=r"(a) : "l"(p));
    return a;
}

__device__ __forceinline__ void cp_async16(uint32_t dst, const void* src) {
    asm volatile("cp.async.cg.shared.global [%0], [%1], 16;"
                 :: "r"(dst), "l"(src));
}
__device__ __forceinline__ void cp_commit() {
    asm volatile("cp.async.commit_group;");
}
__device__ __forceinline__ void cp_wait1() {
    asm volatile("cp.async.wait_group 1;");
}
__device__ __forceinline__ void cp_wait0() {
    asm volatile("cp.async.wait_group 0;");
}

__device__ __forceinline__ void ldsm_x4(uint32_t& r0, uint32_t& r1,
                                        uint32_t& r2, uint32_t& r3,
                                        uint32_t addr) {
    asm volatile("ldmatrix.sync.aligned.m8n8.x4.shared.b16 {%0,%1,%2,%3}, [%4];"
                 : "=r"(r0), "=r"(r1), "=r"(r2), "=r"(r3) : "r"(addr));
}

__device__ __forceinline__ void mma_bf16(float* d, const uint32_t* a,
                                         const uint32_t* b) {
    asm volatile(
        "mma.sync.aligned.m16n8k16.row.col.f32.bf16.bf16.f32 "
        "{%0,%1,%2,%3}, {%4,%5,%6,%7}, {%8,%9}, {%0,%1,%2,%3};"
        : "+f"(d[0]), "+f"(d[1]), "+f"(d[2]), "+f"(d[3])
        : "r"(a[0]), "r"(a[1]), "r"(a[2]), "r"(a[3]), "r"(b[0]), "r"(b[1]));
}

// ---------------------------------------------------------------------------
// Kernel 1: Wc = w0 @ fc_w (512^3 fp32, small)
// ---------------------------------------------------------------------------
__global__ void fuse_weights_kernel(const float* __restrict__ w0,
                                    const float* __restrict__ fc_w) {
    __shared__ float As[16][16];
    __shared__ float Bs[16][16];
    int tx = threadIdx.x, ty = threadIdx.y;
    int h = blockIdx.y * 16 + ty;
    int e = blockIdx.x * 16 + tx;
    float acc = 0.f;
    for (int d0 = 0; d0 < D_SZ; d0 += 16) {
        As[ty][tx] = w0[h * D_SZ + d0 + tx];
        Bs[ty][tx] = fc_w[(d0 + ty) * D_SZ + e];
        __syncthreads();
#pragma unroll
        for (int k = 0; k < 16; k++)
            acc = fmaf(As[ty][k], Bs[k][tx], acc);
        __syncthreads();
    }
    g_Wc[h * D_SZ + e] = acc;
}

// ---------------------------------------------------------------------------
// Kernel 2: bc[h] = dot(w0[h,:], fc_b) + b0[h]
// ---------------------------------------------------------------------------
__global__ void fuse_bias_kernel(const float* __restrict__ w0,
                                 const float* __restrict__ fc_b,
                                 const float* __restrict__ b0) {
    int h = blockIdx.x * blockDim.x + threadIdx.x;
    if (h >= H_SZ) return;
    float acc = b0[h];
    const float* row = w0 + h * D_SZ;
#pragma unroll 8
    for (int d = 0; d < D_SZ; d++)
        acc = fmaf(row[d], fc_b[d], acc);
    g_bc[h] = acc;
}

// ---------------------------------------------------------------------------
// Kernel 3: fp32 -> (hi, lo) bf16 split (vectorized x4)
// ---------------------------------------------------------------------------
__global__ __launch_bounds__(256)
void split_kernel(const float* __restrict__ src,
                  __nv_bfloat16* __restrict__ hi,
                  __nv_bfloat16* __restrict__ lo, int n4) {
    int i = blockIdx.x * blockDim.x + threadIdx.x;
    if (i >= n4) return;
    float4 v = ((const float4*)src)[i];
    __nv_bfloat16 h0 = __float2bfloat16(v.x);
    __nv_bfloat16 h1 = __float2bfloat16(v.y);
    __nv_bfloat16 h2 = __float2bfloat16(v.z);
    __nv_bfloat16 h3 = __float2bfloat16(v.w);
    __nv_bfloat162 hh0; hh0.x = h0; hh0.y = h1;
    __nv_bfloat162 hh1; hh1.x = h2; hh1.y = h3;
    __nv_bfloat162 ll0, ll1;
    ll0.x = __float2bfloat16(v.x - __bfloat162float(h0));
    ll0.y = __float2bfloat16(v.y - __bfloat162float(h1));
    ll1.x = __float2bfloat16(v.z - __bfloat162float(h2));
    ll1.y = __float2bfloat16(v.w - __bfloat162float(h3));
    ((__nv_bfloat162*)hi)[i * 2 + 0] = hh0;
    ((__nv_bfloat162*)hi)[i * 2 + 1] = hh1;
    ((__nv_bfloat162*)lo)[i * 2 + 0] = ll0;
    ((__nv_bfloat162*)lo)[i * 2 + 1] = ll1;
}

// ---------------------------------------------------------------------------
// Kernel 4: HMMA (mma.sync bf16) split GEMM.
//   C[M,512] = Ah@Bh^T + Ah@Bl^T + Al@Bh^T + bias, K'=1536 concat sweep.
//   CTA 128x128, BK=32, 8 warps (4Mx2N), 3-stage cp.async, 2 CTAs/SM.
//   1-D grid, N-index fastest: 4 consecutive CTAs share one A tile (L2 reuse).
// ---------------------------------------------------------------------------
#define ROW_B   80                    // padded smem row stride (bytes)
#define TILE_B  (128 * ROW_B)         // 10240 bytes per operand tile
#define STAGE_B (2 * TILE_B)          // A + B per stage = 20480
#define NSTAGES 3
#define GSMEM   (NSTAGES * STAGE_B)   // 61440 (x2 CTAs = 120KB/SM, fits)

__global__ __launch_bounds__(256, 2)
void gemm_hmma_kernel(const __nv_bfloat16* __restrict__ Ah,
                      const __nv_bfloat16* __restrict__ Al,
                      const __nv_bfloat16* __restrict__ Bh,
                      const __nv_bfloat16* __restrict__ Bl,
                      const float* __restrict__ bias,
                      float* __restrict__ C) {
    extern __shared__ __align__(128) char smem[];
    const uint32_t sb = smem_u32(smem);
    const int tid = threadIdx.x;
    const int lane = tid & 31;
    const int wid = tid >> 5;
    const int wm = wid & 3;            // 0..3  (M direction, 32 rows each)
    const int wn = wid >> 2;           // 0..1  (N direction, 64 cols each)

    // N fastest so blocks sharing an A tile are adjacent in launch order
    const size_t mBase = (size_t)(blockIdx.x >> 2) * 128;
    const size_t nBase = (size_t)(blockIdx.x & 3) * 128;

    float acc[2][8][4];
#pragma unroll
    for (int i = 0; i < 2; i++)
#pragma unroll
        for (int j = 0; j < 8; j++)
#pragma unroll
            for (int k = 0; k < 4; k++) acc[i][j][k] = 0.f;

    // copy indices: this thread moves chunks {tid, tid+256} of A and of B
    const int r0c = tid >> 2, c0c = tid & 3;          // chunk tid
    const int r1c = (tid + 256) >> 2;                 // chunk tid+256

    auto issue = [&](int s) {
        const __nv_bfloat16 *As, *Bs;
        int koff;
        if (s < 16)      { As = Ah; Bs = Bh; koff = s * 32; }
        else if (s < 32) { As = Ah; Bs = Bl; koff = (s - 16) * 32; }
        else             { As = Al; Bs = Bh; koff = (s - 32) * 32; }
        const uint32_t stA = sb + (s % NSTAGES) * STAGE_B;
        const uint32_t stB = stA + TILE_B;
        cp_async16(stA + r0c * ROW_B + c0c * 16,
                   As + (mBase + r0c) * 512 + koff + c0c * 8);
        cp_async16(stA + r1c * ROW_B + c0c * 16,
                   As + (mBase + r1c) * 512 + koff + c0c * 8);
        cp_async16(stB + r0c * ROW_B + c0c * 16,
                   Bs + (nBase + r0c) * 512 + koff + c0c * 8);
        cp_async16(stB + r1c * ROW_B + c0c * 16,
                   Bs + (nBase + r1c) * 512 + koff + c0c * 8);
        cp_commit();
    };

    issue(0);
    issue(1);

    // ldmatrix lane addressing (constant offsets per thread)
    const int a_lr = lane & 15;         // row within 16-row tile
    const int a_kc = lane >> 4;         // 0/1 -> k chunk (+16B)
    const int b_g  = lane >> 3;         // 0..3
    const int b_nr = (b_g >> 1) * 8 + (lane & 7);  // n row within 16
    const int b_kc = b_g & 1;           // k chunk

    for (int s = 0; s < 48; s++) {
        cp_wait1();
        __syncthreads();               // all warps done with stage s-1 buffer
        if (s + 2 < 48) issue(s + 2);

        const uint32_t stA = sb + (s % NSTAGES) * STAGE_B;
        const uint32_t stB = stA + TILE_B;

#pragma unroll
        for (int kk = 0; kk < 2; kk++) {           // two k16 steps
            uint32_t af[2][4];
#pragma unroll
            for (int mi = 0; mi < 2; mi++) {
                uint32_t addr = stA + (wm * 32 + mi * 16 + a_lr) * ROW_B
                              + kk * 32 + a_kc * 16;
                ldsm_x4(af[mi][0], af[mi][1], af[mi][2], af[mi][3], addr);
            }
#pragma unroll
            for (int nj = 0; nj < 4; nj++) {       // 16 n-cols per ldmatrix
                uint32_t b0, b1, b2, b3;
                uint32_t addr = stB + (wn * 64 + nj * 16 + b_nr) * ROW_B
                              + kk * 32 + b_kc * 16;
                ldsm_x4(b0, b1, b2, b3, addr);
                uint32_t bf0[2] = {b0, b1};
                uint32_t bf1[2] = {b2, b3};
#pragma unroll
                for (int mi = 0; mi < 2; mi++) {
                    mma_bf16(acc[mi][nj * 2 + 0], af[mi], bf0);
                    mma_bf16(acc[mi][nj * 2 + 1], af[mi], bf1);
                }
            }
        }
    }
    cp_wait0();

    // Epilogue: bias + store (2 m-tiles x 8 n-subtiles, float2 per row)
    const int rr = lane >> 2;
    const int cc = (lane & 3) * 2;
#pragma unroll
    for (int mi = 0; mi < 2; mi++) {
        const size_t row0 = mBase + wm * 32 + mi * 16 + rr;
#pragma unroll
        for (int ns = 0; ns < 8; ns++) {
            const size_t col = nBase + wn * 64 + ns * 8 + cc;
            const float2 bv = *(const float2*)(bias + col);
            float2 v0, v1;
            v0.x = acc[mi][ns][0] + bv.x;
            v0.y = acc[mi][ns][1] + bv.y;
            v1.x = acc[mi][ns][2] + bv.x;
            v1.y = acc[mi][ns][3] + bv.y;
            *(float2*)(C + row0 * 512 + col) = v0;
            *(float2*)(C + (row0 + 8) * 512 + col) = v1;
        }
    }
}

// ---------------------------------------------------------------------------
// Kernel 5a: IndRNN recurrence, fp32 out (layer 1 -> d_out).  P=32 prefetch.
// ---------------------------------------------------------------------------
#define REC_P 32
__global__ __launch_bounds__(128)
void rec_f32_kernel(const float* __restrict__ pre,
                    float* __restrict__ out,
                    const float* __restrict__ h_init,
                    const float* __restrict__ u,
                    float* __restrict__ h_final) {
    const int idx = blockIdx.x * 128 + threadIdx.x;
    const float uu = u[idx & (H_SZ - 1)];
    float h = h_init[idx];
    float p[REC_P];
#pragma unroll
    for (int j = 0; j < REC_P; j++)
        p[j] = pre[(size_t)j * BH + idx];
    for (int t = 0; t < T_LEN; t += REC_P) {
#pragma unroll
        for (int j = 0; j < REC_P; j++) {
            float cur = p[j];
            int tn = t + REC_P + j;
            if (tn < T_LEN) p[j] = pre[(size_t)tn * BH + idx];
            h = fmaxf(fmaf(uu, h, cur), 0.f);
            out[(size_t)(t + j) * BH + idx] = h;
        }
    }
    h_final[idx] = h;
}

// ---------------------------------------------------------------------------
// Kernel 5b: IndRNN recurrence, writes bf16 (hi, lo) split (layer 0 -> GEMM2)
// ---------------------------------------------------------------------------
__global__ __launch_bounds__(128)
void rec_bf16_kernel(const float* __restrict__ pre,
                     __nv_bfloat16* __restrict__ oh,
                     __nv_bfloat16* __restrict__ ol,
                     const float* __restrict__ h_init,
                     const float* __restrict__ u,
                     float* __restrict__ h_final) {
    const int idx = blockIdx.x * 128 + threadIdx.x;
    const float uu = u[idx & (H_SZ - 1)];
    float h = h_init[idx];
    float p[REC_P];
#pragma unroll
    for (int j = 0; j < REC_P; j++)
        p[j] = pre[(size_t)j * BH + idx];
    for (int t = 0; t < T_LEN; t += REC_P) {
#pragma unroll
        for (int j = 0; j < REC_P; j++) {
            float cur = p[j];
            int tn = t + REC_P + j;
            if (tn < T_LEN) p[j] = pre[(size_t)tn * BH + idx];
            h = fmaxf(fmaf(uu, h, cur), 0.f);
            __nv_bfloat16 hh = __float2bfloat16(h);
            oh[(size_t)(t + j) * BH + idx] = hh;
            ol[(size_t)(t + j) * BH + idx] = __float2bfloat16(h - __bfloat162float(hh));
        }
    }
    h_final[idx] = h;
}

// ---------------------------------------------------------------------------
// Launch
//   inputs: x, hidden, fc_w, fc_b, w0, b0, u0, w1, b1, u1
//   output: [ out1 (T*B*H) | hn (2*B*H) ]
// ---------------------------------------------------------------------------
extern "C" void kernel_launch(void* const* d_in, const int* in_sizes, int n_in,
                              void* d_out, int out_size) {
    const float* x      = (const float*)d_in[0];
    const float* hidden = (const float*)d_in[1];
    const float* fc_w   = (const float*)d_in[2];
    const float* fc_b   = (const float*)d_in[3];
    const float* w0     = (const float*)d_in[4];
    const float* b0     = (const float*)d_in[5];
    const float* u0     = (const float*)d_in[6];
    const float* w1     = (const float*)d_in[7];
    const float* b1     = (const float*)d_in[8];
    const float* u1     = (const float*)d_in[9];
    float* out = (float*)d_out;

    float *Wc, *bc, *pre;
    __nv_bfloat16 *Wch, *Wcl, *w1h, *w1l, *xh, *xl, *o0h, *o0l;
    cudaGetSymbolAddress((void**)&Wc,  g_Wc);
    cudaGetSymbolAddress((void**)&bc,  g_bc);
    cudaGetSymbolAddress((void**)&pre, g_pre);
    cudaGetSymbolAddress((void**)&Wch, g_Wch);
    cudaGetSymbolAddress((void**)&Wcl, g_Wcl);
    cudaGetSymbolAddress((void**)&w1h, g_w1h);
    cudaGetSymbolAddress((void**)&w1l, g_w1l);
    cudaGetSymbolAddress((void**)&xh,  g_xh);
    cudaGetSymbolAddress((void**)&xl,  g_xl);
    cudaGetSymbolAddress((void**)&o0h, g_o0h);
    cudaGetSymbolAddress((void**)&o0l, g_o0l);

    cudaFuncSetAttribute(gemm_hmma_kernel,
                         cudaFuncAttributeMaxDynamicSharedMemorySize, GSMEM);

    // 1) fuse fc into layer-0 weights (fp32), then split weights to bf16 pairs
    fuse_weights_kernel<<<dim3(D_SZ / 16, D_SZ / 16), dim3(16, 16)>>>(w0, fc_w);
    fuse_bias_kernel<<<2, 256>>>(w0, fc_b, b0);
    split_kernel<<<(D_SZ * D_SZ / 4 + 255) / 256, 256>>>(Wc, Wch, Wcl, D_SZ * D_SZ / 4);
    split_kernel<<<(D_SZ * D_SZ / 4 + 255) / 256, 256>>>(w1, w1h, w1l, D_SZ * D_SZ / 4);

    // 2) split x to bf16 pairs
    split_kernel<<<(TBH / 4 + 255) / 256, 256>>>(x, xh, xl, TBH / 4);

    // 3) pre0 = x @ Wc^T + bc
    gemm_hmma_kernel<<<T_LEN * B_SZ / 128 * 4, 256, GSMEM>>>(xh, xl, Wch, Wcl, bc, pre);

    // 4) layer-0 recurrence -> bf16 split out0, h0_final
    rec_bf16_kernel<<<BH / 128, 128>>>(pre, o0h, o0l, hidden, u0, out + TBH);

    // 5) pre1 = out0 @ w1^T + b1
    gemm_hmma_kernel<<<T_LEN * B_SZ / 128 * 4, 256, GSMEM>>>(o0h, o0l, w1h, w1l, b1, pre);

    // 6) layer-1 recurrence -> d_out, h1_final
    rec_f32_kernel<<<BH / 128, 128>>>(pre, out, hidden + BH, u1, out + TBH + BH);
}

// round 6
// speedup vs baseline: 2.6338x; 1.3010x over previous
#include <cuda_runtime.h>
#include <cuda_fp16.h>
#include <cstdint>

// Problem constants
#define T_LEN 1024
#define B_SZ  64
#define D_SZ  512
#define H_SZ  512
#define BH    (B_SZ * H_SZ)          // 32768
#define TBH   (T_LEN * BH)           // 33554432

// ---------------------------------------------------------------------------
// Scratch (static device globals; allocation-free per harness rules)
// ---------------------------------------------------------------------------
__device__ float  g_bc[D_SZ];
__device__ __half g_Wch[D_SZ * D_SZ];    // fused fc->layer0 weight, fp16
__device__ __half g_w1h[D_SZ * D_SZ];    // w1, fp16
__device__ __half g_xh[TBH];
__device__ __half g_xl[TBH];
__device__ __half g_o0h[TBH];
__device__ __half g_o0l[TBH];
__device__ float  g_pre[TBH];

// ---------------------------------------------------------------------------
// sm_80-compatible PTX helpers (cp.async / ldmatrix / mma.sync — base sm_103)
// ---------------------------------------------------------------------------
__device__ __forceinline__ uint32_t smem_u32(const void* p) {
    uint32_t a;
    asm("{ .reg .u64 t; cvta.to.shared.u64 t, %1; cvt.u32.u64 %0, t; }"
        : "=r"(a) : "l"(p));
    return a;
}

__device__ __forceinline__ void cp_async16(uint32_t dst, const void* src) {
    asm volatile("cp.async.cg.shared.global [%0], [%1], 16;"
                 :: "r"(dst), "l"(src));
}
__device__ __forceinline__ void cp_commit() {
    asm volatile("cp.async.commit_group;");
}
__device__ __forceinline__ void cp_wait2() {
    asm volatile("cp.async.wait_group 2;");
}
__device__ __forceinline__ void cp_wait0() {
    asm volatile("cp.async.wait_group 0;");
}

__device__ __forceinline__ void ldsm_x4(uint32_t& r0, uint32_t& r1,
                                        uint32_t& r2, uint32_t& r3,
                                        uint32_t addr) {
    asm volatile("ldmatrix.sync.aligned.m8n8.x4.shared.b16 {%0,%1,%2,%3}, [%4];"
                 : "=r"(r0), "=r"(r1), "=r"(r2), "=r"(r3) : "r"(addr));
}

__device__ __forceinline__ void mma_f16(float* d, const uint32_t* a,
                                        const uint32_t* b) {
    asm volatile(
        "mma.sync.aligned.m16n8k16.row.col.f32.f16.f16.f32 "
        "{%0,%1,%2,%3}, {%4,%5,%6,%7}, {%8,%9}, {%0,%1,%2,%3};"
        : "+f"(d[0]), "+f"(d[1]), "+f"(d[2]), "+f"(d[3])
        : "r"(a[0]), "r"(a[1]), "r"(a[2]), "r"(a[3]), "r"(b[0]), "r"(b[1]));
}

// ---------------------------------------------------------------------------
// Kernel 1: Wch = fp16(w0 @ fc_w)  (512^3 fp32, writes fp16 directly)
// ---------------------------------------------------------------------------
__global__ void fuse_weights_kernel(const float* __restrict__ w0,
                                    const float* __restrict__ fc_w) {
    __shared__ float As[16][16];
    __shared__ float Bs[16][16];
    int tx = threadIdx.x, ty = threadIdx.y;
    int h = blockIdx.y * 16 + ty;
    int e = blockIdx.x * 16 + tx;
    float acc = 0.f;
    for (int d0 = 0; d0 < D_SZ; d0 += 16) {
        As[ty][tx] = w0[h * D_SZ + d0 + tx];
        Bs[ty][tx] = fc_w[(d0 + ty) * D_SZ + e];
        __syncthreads();
#pragma unroll
        for (int k = 0; k < 16; k++)
            acc = fmaf(As[ty][k], Bs[k][tx], acc);
        __syncthreads();
    }
    g_Wch[h * D_SZ + e] = __float2half_rn(acc);
}

// ---------------------------------------------------------------------------
// Kernel 2: bc[h] = dot(w0[h,:], fc_b) + b0[h]
// ---------------------------------------------------------------------------
__global__ void fuse_bias_kernel(const float* __restrict__ w0,
                                 const float* __restrict__ fc_b,
                                 const float* __restrict__ b0) {
    int h = blockIdx.x * blockDim.x + threadIdx.x;
    if (h >= H_SZ) return;
    float acc = b0[h];
    const float* row = w0 + h * D_SZ;
#pragma unroll 8
    for (int d = 0; d < D_SZ; d++)
        acc = fmaf(row[d], fc_b[d], acc);
    g_bc[h] = acc;
}

// ---------------------------------------------------------------------------
// Kernel 2b: fp32 -> fp16 convert (w1)
// ---------------------------------------------------------------------------
__global__ __launch_bounds__(256)
void convert_kernel(const float* __restrict__ src, __half* __restrict__ dst,
                    int n4) {
    int i = blockIdx.x * blockDim.x + threadIdx.x;
    if (i >= n4) return;
    float4 v = ((const float4*)src)[i];
    __half2 a; a.x = __float2half_rn(v.x); a.y = __float2half_rn(v.y);
    __half2 b; b.x = __float2half_rn(v.z); b.y = __float2half_rn(v.w);
    ((__half2*)dst)[i * 2 + 0] = a;
    ((__half2*)dst)[i * 2 + 1] = b;
}

// ---------------------------------------------------------------------------
// Kernel 3: fp32 -> (hi, lo) fp16 split (vectorized x4)
// ---------------------------------------------------------------------------
__global__ __launch_bounds__(256)
void split_kernel(const float* __restrict__ src,
                  __half* __restrict__ hi,
                  __half* __restrict__ lo, int n4) {
    int i = blockIdx.x * blockDim.x + threadIdx.x;
    if (i >= n4) return;
    float4 v = ((const float4*)src)[i];
    __half h0 = __float2half_rn(v.x);
    __half h1 = __float2half_rn(v.y);
    __half h2 = __float2half_rn(v.z);
    __half h3 = __float2half_rn(v.w);
    __half2 hh0; hh0.x = h0; hh0.y = h1;
    __half2 hh1; hh1.x = h2; hh1.y = h3;
    __half2 ll0, ll1;
    ll0.x = __float2half_rn(v.x - __half2float(h0));
    ll0.y = __float2half_rn(v.y - __half2float(h1));
    ll1.x = __float2half_rn(v.z - __half2float(h2));
    ll1.y = __float2half_rn(v.w - __half2float(h3));
    ((__half2*)hi)[i * 2 + 0] = hh0;
    ((__half2*)hi)[i * 2 + 1] = hh1;
    ((__half2*)lo)[i * 2 + 0] = ll0;
    ((__half2*)lo)[i * 2 + 1] = ll1;
}

// ---------------------------------------------------------------------------
// Kernel 4: HMMA (mma.sync fp16) 2-term split GEMM.
//   C[M,512] = (Ah + Al) @ Bh^T + bias  (exact A, fp16-rounded B), K'=1024.
//   CTA 128x128, BK=32, 8 warps (4Mx2N), 4-stage cp.async, 2 CTAs/SM.
//   1-D grid, N-index fastest: 4 consecutive CTAs share one A tile (L2 reuse).
// ---------------------------------------------------------------------------
#define ROW_B   80                    // padded smem row stride (bytes)
#define TILE_B  (128 * ROW_B)         // 10240 bytes per operand tile
#define STAGE_B (2 * TILE_B)          // A + B per stage = 20480
#define NSTAGES 4
#define GSMEM   (NSTAGES * STAGE_B)   // 81920 (x2 CTAs = 160KB/SM, fits)
#define KSTAGES 32                    // K' = 1024 / 32

__global__ __launch_bounds__(256, 2)
void gemm_hmma_kernel(const __half* __restrict__ Ah,
                      const __half* __restrict__ Al,
                      const __half* __restrict__ Bh,
                      const float* __restrict__ bias,
                      float* __restrict__ C) {
    extern __shared__ __align__(128) char smem[];
    const uint32_t sb = smem_u32(smem);
    const int tid = threadIdx.x;
    const int lane = tid & 31;
    const int wid = tid >> 5;
    const int wm = wid & 3;            // 0..3  (M direction, 32 rows each)
    const int wn = wid >> 2;           // 0..1  (N direction, 64 cols each)

    // N fastest so blocks sharing an A tile are adjacent in launch order
    const size_t mBase = (size_t)(blockIdx.x >> 2) * 128;
    const size_t nBase = (size_t)(blockIdx.x & 3) * 128;

    float acc[2][8][4];
#pragma unroll
    for (int i = 0; i < 2; i++)
#pragma unroll
        for (int j = 0; j < 8; j++)
#pragma unroll
            for (int k = 0; k < 4; k++) acc[i][j][k] = 0.f;

    // copy indices: this thread moves chunks {tid, tid+256} of A and of B
    const int r0c = tid >> 2, c0c = tid & 3;          // chunk tid
    const int r1c = (tid + 256) >> 2;                 // chunk tid+256

    auto issue = [&](int s) {
        const __half* As = (s < 16) ? Ah : Al;
        const int koff = (s & 15) * 32;
        const uint32_t stA = sb + (s % NSTAGES) * STAGE_B;
        const uint32_t stB = stA + TILE_B;
        cp_async16(stA + r0c * ROW_B + c0c * 16,
                   As + (mBase + r0c) * 512 + koff + c0c * 8);
        cp_async16(stA + r1c * ROW_B + c0c * 16,
                   As + (mBase + r1c) * 512 + koff + c0c * 8);
        cp_async16(stB + r0c * ROW_B + c0c * 16,
                   Bh + (nBase + r0c) * 512 + koff + c0c * 8);
        cp_async16(stB + r1c * ROW_B + c0c * 16,
                   Bh + (nBase + r1c) * 512 + koff + c0c * 8);
        cp_commit();
    };

    issue(0);
    issue(1);
    issue(2);

    // ldmatrix lane addressing (constant offsets per thread)
    const int a_lr = lane & 15;         // row within 16-row tile
    const int a_kc = lane >> 4;         // 0/1 -> k chunk (+16B)
    const int b_g  = lane >> 3;         // 0..3
    const int b_nr = (b_g >> 1) * 8 + (lane & 7);  // n row within 16
    const int b_kc = b_g & 1;           // k chunk

    for (int s = 0; s < KSTAGES; s++) {
        cp_wait2();
        __syncthreads();               // all warps done with retired buffer
        if (s + 3 < KSTAGES) issue(s + 3);

        const uint32_t stA = sb + (s % NSTAGES) * STAGE_B;
        const uint32_t stB = stA + TILE_B;

#pragma unroll
        for (int kk = 0; kk < 2; kk++) {           // two k16 steps
            uint32_t af[2][4];
#pragma unroll
            for (int mi = 0; mi < 2; mi++) {
                uint32_t addr = stA + (wm * 32 + mi * 16 + a_lr) * ROW_B
                              + kk * 32 + a_kc * 16;
                ldsm_x4(af[mi][0], af[mi][1], af[mi][2], af[mi][3], addr);
            }
#pragma unroll
            for (int nj = 0; nj < 4; nj++) {       // 16 n-cols per ldmatrix
                uint32_t b0, b1, b2, b3;
                uint32_t addr = stB + (wn * 64 + nj * 16 + b_nr) * ROW_B
                              + kk * 32 + b_kc * 16;
                ldsm_x4(b0, b1, b2, b3, addr);
                uint32_t bf0[2] = {b0, b1};
                uint32_t bf1[2] = {b2, b3};
#pragma unroll
                for (int mi = 0; mi < 2; mi++) {
                    mma_f16(acc[mi][nj * 2 + 0], af[mi], bf0);
                    mma_f16(acc[mi][nj * 2 + 1], af[mi], bf1);
                }
            }
        }
    }
    cp_wait0();

    // Epilogue: bias + store (2 m-tiles x 8 n-subtiles, float2 per row)
    const int rr = lane >> 2;
    const int cc = (lane & 3) * 2;
#pragma unroll
    for (int mi = 0; mi < 2; mi++) {
        const size_t row0 = mBase + wm * 32 + mi * 16 + rr;
#pragma unroll
        for (int ns = 0; ns < 8; ns++) {
            const size_t col = nBase + wn * 64 + ns * 8 + cc;
            const float2 bv = *(const float2*)(bias + col);
            float2 v0, v1;
            v0.x = acc[mi][ns][0] + bv.x;
            v0.y = acc[mi][ns][1] + bv.y;
            v1.x = acc[mi][ns][2] + bv.x;
            v1.y = acc[mi][ns][3] + bv.y;
            *(float2*)(C + row0 * 512 + col) = v0;
            *(float2*)(C + (row0 + 8) * 512 + col) = v1;
        }
    }
}

// ---------------------------------------------------------------------------
// Kernel 5a: IndRNN recurrence, fp32 out (layer 1 -> d_out).  P=32 prefetch.
// ---------------------------------------------------------------------------
#define REC_P 32
__global__ __launch_bounds__(128)
void rec_f32_kernel(const float* __restrict__ pre,
                    float* __restrict__ out,
                    const float* __restrict__ h_init,
                    const float* __restrict__ u,
                    float* __restrict__ h_final) {
    const int idx = blockIdx.x * 128 + threadIdx.x;
    const float uu = u[idx & (H_SZ - 1)];
    float h = h_init[idx];
    float p[REC_P];
#pragma unroll
    for (int j = 0; j < REC_P; j++)
        p[j] = pre[(size_t)j * BH + idx];
    for (int t = 0; t < T_LEN; t += REC_P) {
#pragma unroll
        for (int j = 0; j < REC_P; j++) {
            float cur = p[j];
            int tn = t + REC_P + j;
            if (tn < T_LEN) p[j] = pre[(size_t)tn * BH + idx];
            h = fmaxf(fmaf(uu, h, cur), 0.f);
            out[(size_t)(t + j) * BH + idx] = h;
        }
    }
    h_final[idx] = h;
}

// ---------------------------------------------------------------------------
// Kernel 5b: IndRNN recurrence, writes fp16 (hi, lo) split (layer 0 -> GEMM2)
// ---------------------------------------------------------------------------
__global__ __launch_bounds__(128)
void rec_f16_kernel(const float* __restrict__ pre,
                    __half* __restrict__ oh,
                    __half* __restrict__ ol,
                    const float* __restrict__ h_init,
                    const float* __restrict__ u,
                    float* __restrict__ h_final) {
    const int idx = blockIdx.x * 128 + threadIdx.x;
    const float uu = u[idx & (H_SZ - 1)];
    float h = h_init[idx];
    float p[REC_P];
#pragma unroll
    for (int j = 0; j < REC_P; j++)
        p[j] = pre[(size_t)j * BH + idx];
    for (int t = 0; t < T_LEN; t += REC_P) {
#pragma unroll
        for (int j = 0; j < REC_P; j++) {
            float cur = p[j];
            int tn = t + REC_P + j;
            if (tn < T_LEN) p[j] = pre[(size_t)tn * BH + idx];
            h = fmaxf(fmaf(uu, h, cur), 0.f);
            __half hh = __float2half_rn(h);
            oh[(size_t)(t + j) * BH + idx] = hh;
            ol[(size_t)(t + j) * BH + idx] = __float2half_rn(h - __half2float(hh));
        }
    }
    h_final[idx] = h;
}

// ---------------------------------------------------------------------------
// Launch
//   inputs: x, hidden, fc_w, fc_b, w0, b0, u0, w1, b1, u1
//   output: [ out1 (T*B*H) | hn (2*B*H) ]
// ---------------------------------------------------------------------------
extern "C" void kernel_launch(void* const* d_in, const int* in_sizes, int n_in,
                              void* d_out, int out_size) {
    const float* x      = (const float*)d_in[0];
    const float* hidden = (const float*)d_in[1];
    const float* fc_w   = (const float*)d_in[2];
    const float* fc_b   = (const float*)d_in[3];
    const float* w0     = (const float*)d_in[4];
    const float* b0     = (const float*)d_in[5];
    const float* u0     = (const float*)d_in[6];
    const float* w1     = (const float*)d_in[7];
    const float* b1     = (const float*)d_in[8];
    const float* u1     = (const float*)d_in[9];
    float* out = (float*)d_out;

    float *bc, *pre;
    __half *Wch, *w1h, *xh, *xl, *o0h, *o0l;
    cudaGetSymbolAddress((void**)&bc,  g_bc);
    cudaGetSymbolAddress((void**)&pre, g_pre);
    cudaGetSymbolAddress((void**)&Wch, g_Wch);
    cudaGetSymbolAddress((void**)&w1h, g_w1h);
    cudaGetSymbolAddress((void**)&xh,  g_xh);
    cudaGetSymbolAddress((void**)&xl,  g_xl);
    cudaGetSymbolAddress((void**)&o0h, g_o0h);
    cudaGetSymbolAddress((void**)&o0l, g_o0l);

    cudaFuncSetAttribute(gemm_hmma_kernel,
                         cudaFuncAttributeMaxDynamicSharedMemorySize, GSMEM);

    // 1) fuse fc into layer-0 weights -> fp16 directly; bias; convert w1
    fuse_weights_kernel<<<dim3(D_SZ / 16, D_SZ / 16), dim3(16, 16)>>>(w0, fc_w);
    fuse_bias_kernel<<<2, 256>>>(w0, fc_b, b0);
    convert_kernel<<<(D_SZ * D_SZ / 4 + 255) / 256, 256>>>(w1, w1h, D_SZ * D_SZ / 4);

    // 2) split x to fp16 (hi, lo) pairs
    split_kernel<<<(TBH / 4 + 255) / 256, 256>>>(x, xh, xl, TBH / 4);

    // 3) pre0 = x @ Wch^T + bc
    gemm_hmma_kernel<<<T_LEN * B_SZ / 128 * 4, 256, GSMEM>>>(xh, xl, Wch, bc, pre);

    // 4) layer-0 recurrence -> fp16 split out0, h0_final
    rec_f16_kernel<<<BH / 128, 128>>>(pre, o0h, o0l, hidden, u0, out + TBH);

    // 5) pre1 = out0 @ w1h^T + b1
    gemm_hmma_kernel<<<T_LEN * B_SZ / 128 * 4, 256, GSMEM>>>(o0h, o0l, w1h, b1, pre);

    // 6) layer-1 recurrence -> d_out, h1_final
    rec_f32_kernel<<<BH / 128, 128>>>(pre, out, hidden + BH, u1, out + TBH + BH);
}

// round 7
// speedup vs baseline: 3.7879x; 1.4382x over previous
#include <cuda_runtime.h>
#include <cuda_fp16.h>
#include <cstdint>

// Problem constants
#define T_LEN 1024
#define B_SZ  64
#define D_SZ  512
#define H_SZ  512
#define BH    (B_SZ * H_SZ)          // 32768
#define TBH   (T_LEN * BH)           // 33554432

// ---------------------------------------------------------------------------
// Scratch (static device globals; allocation-free per harness rules)
// ---------------------------------------------------------------------------
__device__ float  g_bc[D_SZ];
__device__ __half g_Wch[D_SZ * D_SZ];    // fused fc->layer0 weight, fp16
__device__ __half g_w1h[D_SZ * D_SZ];    // w1, fp16
__device__ __half g_xh[TBH];             // fp16(x)
__device__ __half g_o0h[TBH];            // fp16(out0)
__device__ __half g_pre[TBH];            // fp16 pre-activations (both layers)

// ---------------------------------------------------------------------------
// sm_80-compatible PTX helpers (cp.async / ldmatrix / mma.sync — base sm_103)
// ---------------------------------------------------------------------------
__device__ __forceinline__ uint32_t smem_u32(const void* p) {
    uint32_t a;
    asm("{ .reg .u64 t; cvta.to.shared.u64 t, %1; cvt.u32.u64 %0, t; }"
        : "=r"(a) : "l"(p));
    return a;
}

__device__ __forceinline__ void cp_async16(uint32_t dst, const void* src) {
    asm volatile("cp.async.cg.shared.global [%0], [%1], 16;"
                 :: "r"(dst), "l"(src));
}
__device__ __forceinline__ void cp_commit() {
    asm volatile("cp.async.commit_group;");
}
__device__ __forceinline__ void cp_wait2() {
    asm volatile("cp.async.wait_group 2;");
}
__device__ __forceinline__ void cp_wait0() {
    asm volatile("cp.async.wait_group 0;");
}

__device__ __forceinline__ void ldsm_x4(uint32_t& r0, uint32_t& r1,
                                        uint32_t& r2, uint32_t& r3,
                                        uint32_t addr) {
    asm volatile("ldmatrix.sync.aligned.m8n8.x4.shared.b16 {%0,%1,%2,%3}, [%4];"
                 : "=r"(r0), "=r"(r1), "=r"(r2), "=r"(r3) : "r"(addr));
}

__device__ __forceinline__ void mma_f16(float* d, const uint32_t* a,
                                        const uint32_t* b) {
    asm volatile(
        "mma.sync.aligned.m16n8k16.row.col.f32.f16.f16.f32 "
        "{%0,%1,%2,%3}, {%4,%5,%6,%7}, {%8,%9}, {%0,%1,%2,%3};"
        : "+f"(d[0]), "+f"(d[1]), "+f"(d[2]), "+f"(d[3])
        : "r"(a[0]), "r"(a[1]), "r"(a[2]), "r"(a[3]), "r"(b[0]), "r"(b[1]));
}

// ---------------------------------------------------------------------------
// Kernel 1: Wch = fp16(w0 @ fc_w)  (512^3 fp32, writes fp16 directly)
// ---------------------------------------------------------------------------
__global__ void fuse_weights_kernel(const float* __restrict__ w0,
                                    const float* __restrict__ fc_w) {
    __shared__ float As[16][16];
    __shared__ float Bs[16][16];
    int tx = threadIdx.x, ty = threadIdx.y;
    int h = blockIdx.y * 16 + ty;
    int e = blockIdx.x * 16 + tx;
    float acc = 0.f;
    for (int d0 = 0; d0 < D_SZ; d0 += 16) {
        As[ty][tx] = w0[h * D_SZ + d0 + tx];
        Bs[ty][tx] = fc_w[(d0 + ty) * D_SZ + e];
        __syncthreads();
#pragma unroll
        for (int k = 0; k < 16; k++)
            acc = fmaf(As[ty][k], Bs[k][tx], acc);
        __syncthreads();
    }
    g_Wch[h * D_SZ + e] = __float2half_rn(acc);
}

// ---------------------------------------------------------------------------
// Kernel 2: bc[h] = dot(w0[h,:], fc_b) + b0[h]
// ---------------------------------------------------------------------------
__global__ void fuse_bias_kernel(const float* __restrict__ w0,
                                 const float* __restrict__ fc_b,
                                 const float* __restrict__ b0) {
    int h = blockIdx.x * blockDim.x + threadIdx.x;
    if (h >= H_SZ) return;
    float acc = b0[h];
    const float* row = w0 + h * D_SZ;
#pragma unroll 8
    for (int d = 0; d < D_SZ; d++)
        acc = fmaf(row[d], fc_b[d], acc);
    g_bc[h] = acc;
}

// ---------------------------------------------------------------------------
// Kernel 3: fp32 -> fp16 convert (w1, x)
// ---------------------------------------------------------------------------
__global__ __launch_bounds__(256)
void convert_kernel(const float* __restrict__ src, __half* __restrict__ dst,
                    int n4) {
    int i = blockIdx.x * blockDim.x + threadIdx.x;
    if (i >= n4) return;
    float4 v = ((const float4*)src)[i];
    __half2 a; a.x = __float2half_rn(v.x); a.y = __float2half_rn(v.y);
    __half2 b; b.x = __float2half_rn(v.z); b.y = __float2half_rn(v.w);
    ((__half2*)dst)[i * 2 + 0] = a;
    ((__half2*)dst)[i * 2 + 1] = b;
}

// ---------------------------------------------------------------------------
// Kernel 4: HMMA (mma.sync fp16) GEMM, fp16 in / fp16 out.
//   C[M,512] = A @ B^T + bias, K=512.
//   CTA 128x128, BK=32, 8 warps (4Mx2N), 4-stage cp.async, 2 CTAs/SM.
//   1-D grid, N-index fastest: 4 consecutive CTAs share one A tile (L2 reuse).
// ---------------------------------------------------------------------------
#define ROW_B   80                    // padded smem row stride (bytes)
#define TILE_B  (128 * ROW_B)         // 10240 bytes per operand tile
#define STAGE_B (2 * TILE_B)          // A + B per stage = 20480
#define NSTAGES 4
#define GSMEM   (NSTAGES * STAGE_B)   // 81920 (x2 CTAs = 160KB/SM, fits)
#define KSTAGES 16                    // K = 512 / 32

__global__ __launch_bounds__(256, 2)
void gemm_hmma_kernel(const __half* __restrict__ A,
                      const __half* __restrict__ B,
                      const float* __restrict__ bias,
                      __half* __restrict__ C) {
    extern __shared__ __align__(128) char smem[];
    const uint32_t sb = smem_u32(smem);
    const int tid = threadIdx.x;
    const int lane = tid & 31;
    const int wid = tid >> 5;
    const int wm = wid & 3;            // 0..3  (M direction, 32 rows each)
    const int wn = wid >> 2;           // 0..1  (N direction, 64 cols each)

    // N fastest so blocks sharing an A tile are adjacent in launch order
    const size_t mBase = (size_t)(blockIdx.x >> 2) * 128;
    const size_t nBase = (size_t)(blockIdx.x & 3) * 128;

    float acc[2][8][4];
#pragma unroll
    for (int i = 0; i < 2; i++)
#pragma unroll
        for (int j = 0; j < 8; j++)
#pragma unroll
            for (int k = 0; k < 4; k++) acc[i][j][k] = 0.f;

    // copy indices: this thread moves chunks {tid, tid+256} of A and of B
    const int r0c = tid >> 2, c0c = tid & 3;          // chunk tid
    const int r1c = (tid + 256) >> 2;                 // chunk tid+256

    auto issue = [&](int s) {
        const int koff = s * 32;
        const uint32_t stA = sb + (s % NSTAGES) * STAGE_B;
        const uint32_t stB = stA + TILE_B;
        cp_async16(stA + r0c * ROW_B + c0c * 16,
                   A + (mBase + r0c) * 512 + koff + c0c * 8);
        cp_async16(stA + r1c * ROW_B + c0c * 16,
                   A + (mBase + r1c) * 512 + koff + c0c * 8);
        cp_async16(stB + r0c * ROW_B + c0c * 16,
                   B + (nBase + r0c) * 512 + koff + c0c * 8);
        cp_async16(stB + r1c * ROW_B + c0c * 16,
                   B + (nBase + r1c) * 512 + koff + c0c * 8);
        cp_commit();
    };

    issue(0);
    issue(1);
    issue(2);

    // ldmatrix lane addressing (constant offsets per thread)
    const int a_lr = lane & 15;         // row within 16-row tile
    const int a_kc = lane >> 4;         // 0/1 -> k chunk (+16B)
    const int b_g  = lane >> 3;         // 0..3
    const int b_nr = (b_g >> 1) * 8 + (lane & 7);  // n row within 16
    const int b_kc = b_g & 1;           // k chunk

    for (int s = 0; s < KSTAGES; s++) {
        cp_wait2();
        __syncthreads();               // all warps done with retired buffer
        if (s + 3 < KSTAGES) issue(s + 3);

        const uint32_t stA = sb + (s % NSTAGES) * STAGE_B;
        const uint32_t stB = stA + TILE_B;

#pragma unroll
        for (int kk = 0; kk < 2; kk++) {           // two k16 steps
            uint32_t af[2][4];
#pragma unroll
            for (int mi = 0; mi < 2; mi++) {
                uint32_t addr = stA + (wm * 32 + mi * 16 + a_lr) * ROW_B
                              + kk * 32 + a_kc * 16;
                ldsm_x4(af[mi][0], af[mi][1], af[mi][2], af[mi][3], addr);
            }
#pragma unroll
            for (int nj = 0; nj < 4; nj++) {       // 16 n-cols per ldmatrix
                uint32_t b0, b1, b2, b3;
                uint32_t addr = stB + (wn * 64 + nj * 16 + b_nr) * ROW_B
                              + kk * 32 + b_kc * 16;
                ldsm_x4(b0, b1, b2, b3, addr);
                uint32_t bf0[2] = {b0, b1};
                uint32_t bf1[2] = {b2, b3};
#pragma unroll
                for (int mi = 0; mi < 2; mi++) {
                    mma_f16(acc[mi][nj * 2 + 0], af[mi], bf0);
                    mma_f16(acc[mi][nj * 2 + 1], af[mi], bf1);
                }
            }
        }
    }
    cp_wait0();

    // Epilogue: bias + fp16 store (2 m-tiles x 8 n-subtiles, half2 per row)
    const int rr = lane >> 2;
    const int cc = (lane & 3) * 2;
#pragma unroll
    for (int mi = 0; mi < 2; mi++) {
        const size_t row0 = mBase + wm * 32 + mi * 16 + rr;
#pragma unroll
        for (int ns = 0; ns < 8; ns++) {
            const size_t col = nBase + wn * 64 + ns * 8 + cc;
            const float2 bv = *(const float2*)(bias + col);
            __half2 v0 = __floats2half2_rn(acc[mi][ns][0] + bv.x,
                                           acc[mi][ns][1] + bv.y);
            __half2 v1 = __floats2half2_rn(acc[mi][ns][2] + bv.x,
                                           acc[mi][ns][3] + bv.y);
            *(__half2*)(C + row0 * 512 + col) = v0;
            *(__half2*)(C + (row0 + 8) * 512 + col) = v1;
        }
    }
}

// ---------------------------------------------------------------------------
// Kernel 5a: IndRNN recurrence, fp16 pre -> fp16 out (layer 0)
// ---------------------------------------------------------------------------
#define REC_P 32
__global__ __launch_bounds__(128)
void rec_h2h_kernel(const __half* __restrict__ pre,
                    __half* __restrict__ out,
                    const float* __restrict__ h_init,
                    const float* __restrict__ u,
                    float* __restrict__ h_final) {
    const int idx = blockIdx.x * 128 + threadIdx.x;
    const float uu = u[idx & (H_SZ - 1)];
    float h = h_init[idx];
    __half p[REC_P];
#pragma unroll
    for (int j = 0; j < REC_P; j++)
        p[j] = pre[(size_t)j * BH + idx];
    for (int t = 0; t < T_LEN; t += REC_P) {
#pragma unroll
        for (int j = 0; j < REC_P; j++) {
            float cur = __half2float(p[j]);
            int tn = t + REC_P + j;
            if (tn < T_LEN) p[j] = pre[(size_t)tn * BH + idx];
            h = fmaxf(fmaf(uu, h, cur), 0.f);
            out[(size_t)(t + j) * BH + idx] = __float2half_rn(h);
        }
    }
    h_final[idx] = h;
}

// ---------------------------------------------------------------------------
// Kernel 5b: IndRNN recurrence, fp16 pre -> fp32 out (layer 1 -> d_out)
// ---------------------------------------------------------------------------
__global__ __launch_bounds__(128)
void rec_h2f_kernel(const __half* __restrict__ pre,
                    float* __restrict__ out,
                    const float* __restrict__ h_init,
                    const float* __restrict__ u,
                    float* __restrict__ h_final) {
    const int idx = blockIdx.x * 128 + threadIdx.x;
    const float uu = u[idx & (H_SZ - 1)];
    float h = h_init[idx];
    __half p[REC_P];
#pragma unroll
    for (int j = 0; j < REC_P; j++)
        p[j] = pre[(size_t)j * BH + idx];
    for (int t = 0; t < T_LEN; t += REC_P) {
#pragma unroll
        for (int j = 0; j < REC_P; j++) {
            float cur = __half2float(p[j]);
            int tn = t + REC_P + j;
            if (tn < T_LEN) p[j] = pre[(size_t)tn * BH + idx];
            h = fmaxf(fmaf(uu, h, cur), 0.f);
            out[(size_t)(t + j) * BH + idx] = h;
        }
    }
    h_final[idx] = h;
}

// ---------------------------------------------------------------------------
// Launch
//   inputs: x, hidden, fc_w, fc_b, w0, b0, u0, w1, b1, u1
//   output: [ out1 (T*B*H) | hn (2*B*H) ]
// ---------------------------------------------------------------------------
extern "C" void kernel_launch(void* const* d_in, const int* in_sizes, int n_in,
                              void* d_out, int out_size) {
    const float* x      = (const float*)d_in[0];
    const float* hidden = (const float*)d_in[1];
    const float* fc_w   = (const float*)d_in[2];
    const float* fc_b   = (const float*)d_in[3];
    const float* w0     = (const float*)d_in[4];
    const float* b0     = (const float*)d_in[5];
    const float* u0     = (const float*)d_in[6];
    const float* w1     = (const float*)d_in[7];
    const float* b1     = (const float*)d_in[8];
    const float* u1     = (const float*)d_in[9];
    float* out = (float*)d_out;

    float *bc;
    __half *Wch, *w1h, *xh, *o0h, *pre;
    cudaGetSymbolAddress((void**)&bc,  g_bc);
    cudaGetSymbolAddress((void**)&pre, g_pre);
    cudaGetSymbolAddress((void**)&Wch, g_Wch);
    cudaGetSymbolAddress((void**)&w1h, g_w1h);
    cudaGetSymbolAddress((void**)&xh,  g_xh);
    cudaGetSymbolAddress((void**)&o0h, g_o0h);

    cudaFuncSetAttribute(gemm_hmma_kernel,
                         cudaFuncAttributeMaxDynamicSharedMemorySize, GSMEM);

    // 1) fuse fc into layer-0 weights -> fp16 directly; bias; convert w1
    fuse_weights_kernel<<<dim3(D_SZ / 16, D_SZ / 16), dim3(16, 16)>>>(w0, fc_w);
    fuse_bias_kernel<<<2, 256>>>(w0, fc_b, b0);
    convert_kernel<<<(D_SZ * D_SZ / 4 + 255) / 256, 256>>>(w1, w1h, D_SZ * D_SZ / 4);

    // 2) convert x to fp16
    convert_kernel<<<(TBH / 4 + 255) / 256, 256>>>(x, xh, TBH / 4);

    // 3) pre0 = x @ Wch^T + bc   (fp16 out)
    gemm_hmma_kernel<<<T_LEN * B_SZ / 128 * 4, 256, GSMEM>>>(xh, Wch, bc, pre);

    // 4) layer-0 recurrence -> fp16 out0, h0_final
    rec_h2h_kernel<<<BH / 128, 128>>>(pre, o0h, hidden, u0, out + TBH);

    // 5) pre1 = out0 @ w1h^T + b1   (fp16 out)
    gemm_hmma_kernel<<<T_LEN * B_SZ / 128 * 4, 256, GSMEM>>>(o0h, w1h, b1, pre);

    // 6) layer-1 recurrence -> d_out, h1_final
    rec_h2f_kernel<<<BH / 128, 128>>>(pre, out, hidden + BH, u1, out + TBH + BH);
}

// round 9
// speedup vs baseline: 4.3167x; 1.1396x over previous
#include <cuda_runtime.h>
#include <cuda_fp16.h>
#include <cstdint>

// Problem constants
#define T_LEN 1024
#define B_SZ  64
#define D_SZ  512
#define H_SZ  512
#define BH    (B_SZ * H_SZ)          // 32768
#define TBH   (T_LEN * BH)           // 33554432

// ---------------------------------------------------------------------------
// Scratch (static device globals; allocation-free per harness rules)
// ---------------------------------------------------------------------------
__device__ float  g_bc[D_SZ];
__device__ __half g_Wch[D_SZ * D_SZ];    // fused fc->layer0 weight, fp16
__device__ __half g_w1h[D_SZ * D_SZ];    // w1, fp16
__device__ __half g_xh[TBH];             // fp16(x)
__device__ __half g_o0h[TBH];            // fp16(out0)
__device__ __half g_pre[TBH];            // fp16 pre-activations (both layers)

// ---------------------------------------------------------------------------
// sm_80-compatible PTX helpers (cp.async / ldmatrix / mma.sync — base sm_103)
// ---------------------------------------------------------------------------
__device__ __forceinline__ uint32_t smem_u32(const void* p) {
    uint32_t a;
    asm("{ .reg .u64 t; cvta.to.shared.u64 t, %1; cvt.u32.u64 %0, t; }"
        : "=r"(a) : "l"(p));
    return a;
}

__device__ __forceinline__ void cp_async16(uint32_t dst, const void* src) {
    asm volatile("cp.async.cg.shared.global [%0], [%1], 16;"
                 :: "r"(dst), "l"(src));
}
__device__ __forceinline__ void cp_commit() {
    asm volatile("cp.async.commit_group;");
}
__device__ __forceinline__ void cp_wait1() {
    asm volatile("cp.async.wait_group 1;");
}
__device__ __forceinline__ void cp_wait6() {
    asm volatile("cp.async.wait_group 6;");
}
__device__ __forceinline__ void cp_wait0() {
    asm volatile("cp.async.wait_group 0;");
}

__device__ __forceinline__ void ldsm_x4(uint32_t& r0, uint32_t& r1,
                                        uint32_t& r2, uint32_t& r3,
                                        uint32_t addr) {
    asm volatile("ldmatrix.sync.aligned.m8n8.x4.shared.b16 {%0,%1,%2,%3}, [%4];"
                 : "=r"(r0), "=r"(r1), "=r"(r2), "=r"(r3) : "r"(addr));
}

__device__ __forceinline__ void mma_f16(float* d, const uint32_t* a,
                                        const uint32_t* b) {
    asm volatile(
        "mma.sync.aligned.m16n8k16.row.col.f32.f16.f16.f32 "
        "{%0,%1,%2,%3}, {%4,%5,%6,%7}, {%8,%9}, {%0,%1,%2,%3};"
        : "+f"(d[0]), "+f"(d[1]), "+f"(d[2]), "+f"(d[3])
        : "r"(a[0]), "r"(a[1]), "r"(a[2]), "r"(a[3]), "r"(b[0]), "r"(b[1]));
}

// ---------------------------------------------------------------------------
// Kernel 1: Wch = fp16(w0 @ fc_w)  (512^3 fp32, 64x64 tiles, float4 loads)
// ---------------------------------------------------------------------------
__global__ __launch_bounds__(256)
void fuse_weights_kernel(const float* __restrict__ w0,
                         const float* __restrict__ fc_w) {
    __shared__ float As[16][64];   // As[k][m]
    __shared__ float Bs[16][64];   // Bs[k][n]
    const int tid = threadIdx.x;
    const int ty = tid >> 4, tx = tid & 15;
    const int hBase = blockIdx.y * 64;
    const int eBase = blockIdx.x * 64;

    float acc[4][4];
#pragma unroll
    for (int i = 0; i < 4; i++)
#pragma unroll
        for (int j = 0; j < 4; j++) acc[i][j] = 0.f;

    for (int k0 = 0; k0 < D_SZ; k0 += 16) {
        {
            int id = tid * 4;
            int row = id >> 4, col = id & 15;
            float4 v = *(const float4*)(w0 + (hBase + row) * D_SZ + k0 + col);
            As[col + 0][row] = v.x;
            As[col + 1][row] = v.y;
            As[col + 2][row] = v.z;
            As[col + 3][row] = v.w;
        }
        {
            int id = tid * 4;
            int r = id >> 6, c = id & 63;
            float4 v = *(const float4*)(fc_w + (k0 + r) * D_SZ + eBase + c);
            Bs[r][c + 0] = v.x;
            Bs[r][c + 1] = v.y;
            Bs[r][c + 2] = v.z;
            Bs[r][c + 3] = v.w;
        }
        __syncthreads();
#pragma unroll
        for (int k = 0; k < 16; k++) {
            float ra[4], rb[4];
#pragma unroll
            for (int i = 0; i < 4; i++) ra[i] = As[k][ty * 4 + i];
#pragma unroll
            for (int j = 0; j < 4; j++) rb[j] = Bs[k][tx * 4 + j];
#pragma unroll
            for (int i = 0; i < 4; i++)
#pragma unroll
                for (int j = 0; j < 4; j++)
                    acc[i][j] = fmaf(ra[i], rb[j], acc[i][j]);
        }
        __syncthreads();
    }
#pragma unroll
    for (int i = 0; i < 4; i++)
#pragma unroll
        for (int j = 0; j < 4; j++)
            g_Wch[(hBase + ty * 4 + i) * D_SZ + eBase + tx * 4 + j] =
                __float2half_rn(acc[i][j]);
}

// ---------------------------------------------------------------------------
// Kernel 2: bc[h] = dot(w0[h,:], fc_b) + b0[h]
// ---------------------------------------------------------------------------
__global__ void fuse_bias_kernel(const float* __restrict__ w0,
                                 const float* __restrict__ fc_b,
                                 const float* __restrict__ b0) {
    int h = blockIdx.x * blockDim.x + threadIdx.x;
    if (h >= H_SZ) return;
    float acc = b0[h];
    const float* row = w0 + h * D_SZ;
#pragma unroll 8
    for (int d = 0; d < D_SZ; d++)
        acc = fmaf(row[d], fc_b[d], acc);
    g_bc[h] = acc;
}

// ---------------------------------------------------------------------------
// Kernel 3: fp32 -> fp16 convert (w1, x)
// ---------------------------------------------------------------------------
__global__ __launch_bounds__(256)
void convert_kernel(const float* __restrict__ src, __half* __restrict__ dst,
                    int n4) {
    int i = blockIdx.x * blockDim.x + threadIdx.x;
    if (i >= n4) return;
    float4 v = ((const float4*)src)[i];
    __half2 a; a.x = __float2half_rn(v.x); a.y = __float2half_rn(v.y);
    __half2 b; b.x = __float2half_rn(v.z); b.y = __float2half_rn(v.w);
    ((__half2*)dst)[i * 2 + 0] = a;
    ((__half2*)dst)[i * 2 + 1] = b;
}

// ---------------------------------------------------------------------------
// Kernel 4: HMMA (mma.sync fp16) GEMM, fp16 in / fp16 out.
//   C[M,512] = A @ B^T + bias, K=512.
//   CTA 128x128, BK=64, 8 warps (4Mx2N), 3-stage cp.async, 2 CTAs/SM.
//   Empty commit groups on non-issuing iterations keep wait_group arithmetic
//   exact through the tail (no stage ever consumed before its group retires).
// ---------------------------------------------------------------------------
#define ROW_B   144                   // 64 halves = 128B + 16B pad
#define TILE_B  (128 * ROW_B)         // 18432 bytes per operand tile
#define STAGE_B (2 * TILE_B)          // A + B per stage = 36864
#define NSTAGES 3
#define GSMEM   (NSTAGES * STAGE_B)   // 110592 (x2 CTAs = 216KB/SM, fits 228KB)
#define KSTAGES 8                     // K = 512 / 64

__global__ __launch_bounds__(256, 2)
void gemm_hmma_kernel(const __half* __restrict__ A,
                      const __half* __restrict__ B,
                      const float* __restrict__ bias,
                      __half* __restrict__ C) {
    extern __shared__ __align__(128) char smem[];
    const uint32_t sb = smem_u32(smem);
    const int tid = threadIdx.x;
    const int lane = tid & 31;
    const int wid = tid >> 5;
    const int wm = wid & 3;            // 0..3  (M direction, 32 rows each)
    const int wn = wid >> 2;           // 0..1  (N direction, 64 cols each)

    // N fastest so blocks sharing an A tile are adjacent in launch order
    const size_t mBase = (size_t)(blockIdx.x >> 2) * 128;
    const size_t nBase = (size_t)(blockIdx.x & 3) * 128;

    float acc[2][8][4];
#pragma unroll
    for (int i = 0; i < 2; i++)
#pragma unroll
        for (int j = 0; j < 8; j++)
#pragma unroll
            for (int k = 0; k < 4; k++) acc[i][j][k] = 0.f;

    auto issue = [&](int s) {
        const int koff = s * 64;
        const uint32_t stA = sb + (s % NSTAGES) * STAGE_B;
        const uint32_t stB = stA + TILE_B;
        // 128 rows x 8 chunks (16B) per tile = 1024 chunks; 4 per thread
#pragma unroll
        for (int j = 0; j < 4; j++) {
            const int c = tid + j * 256;
            const int row = c >> 3, col = c & 7;
            cp_async16(stA + row * ROW_B + col * 16,
                       A + (mBase + row) * 512 + koff + col * 8);
            cp_async16(stB + row * ROW_B + col * 16,
                       B + (nBase + row) * 512 + koff + col * 8);
        }
        cp_commit();
    };

    issue(0);
    issue(1);

    // ldmatrix lane addressing (constant offsets per thread)
    const int a_lr = lane & 15;         // row within 16-row tile
    const int a_kc = lane >> 4;         // 0/1 -> k chunk (+16B)
    const int b_g  = lane >> 3;         // 0..3
    const int b_nr = (b_g >> 1) * 8 + (lane & 7);  // n row within 16
    const int b_kc = b_g & 1;           // k chunk

    for (int s = 0; s < KSTAGES; s++) {
        cp_wait1();                    // group s complete (2+s issued, wait<=1)
        __syncthreads();               // all warps done with retired buffer
        if (s + 2 < KSTAGES) issue(s + 2);
        else cp_commit();              // empty group: keeps wait arithmetic exact

        const uint32_t stA = sb + (s % NSTAGES) * STAGE_B;
        const uint32_t stB = stA + TILE_B;

#pragma unroll
        for (int kk = 0; kk < 4; kk++) {           // four k16 steps
            uint32_t af[2][4];
#pragma unroll
            for (int mi = 0; mi < 2; mi++) {
                uint32_t addr = stA + (wm * 32 + mi * 16 + a_lr) * ROW_B
                              + kk * 32 + a_kc * 16;
                ldsm_x4(af[mi][0], af[mi][1], af[mi][2], af[mi][3], addr);
            }
#pragma unroll
            for (int nj = 0; nj < 4; nj++) {       // 16 n-cols per ldmatrix
                uint32_t b0, b1, b2, b3;
                uint32_t addr = stB + (wn * 64 + nj * 16 + b_nr) * ROW_B
                              + kk * 32 + b_kc * 16;
                ldsm_x4(b0, b1, b2, b3, addr);
                uint32_t bf0[2] = {b0, b1};
                uint32_t bf1[2] = {b2, b3};
#pragma unroll
                for (int mi = 0; mi < 2; mi++) {
                    mma_f16(acc[mi][nj * 2 + 0], af[mi], bf0);
                    mma_f16(acc[mi][nj * 2 + 1], af[mi], bf1);
                }
            }
        }
    }
    cp_wait0();

    // Epilogue: bias + fp16 store (2 m-tiles x 8 n-subtiles, half2 per row)
    const int rr = lane >> 2;
    const int cc = (lane & 3) * 2;
#pragma unroll
    for (int mi = 0; mi < 2; mi++) {
        const size_t row0 = mBase + wm * 32 + mi * 16 + rr;
#pragma unroll
        for (int ns = 0; ns < 8; ns++) {
            const size_t col = nBase + wn * 64 + ns * 8 + cc;
            const float2 bv = *(const float2*)(bias + col);
            __half2 v0 = __floats2half2_rn(acc[mi][ns][0] + bv.x,
                                           acc[mi][ns][1] + bv.y);
            __half2 v1 = __floats2half2_rn(acc[mi][ns][2] + bv.x,
                                           acc[mi][ns][3] + bv.y);
            *(__half2*)(C + row0 * 512 + col) = v0;
            *(__half2*)(C + (row0 + 8) * 512 + col) = v1;
        }
    }
}

// ---------------------------------------------------------------------------
// Kernels 5: IndRNN recurrence with cp.async smem staging.
//   128 threads = 128 channels/block, 256 blocks. 8 stages x 16 timesteps.
//   Empty commits on the tail keep wait_group 6 <=> "stage s retired" exact.
// ---------------------------------------------------------------------------
#define RTC  16                       // timesteps per stage
#define RNS  8                        // stages
#define RSTG (128 * RTC * 2)          // 4096 bytes per stage
#define RSM  (RNS * RSTG)             // 32768 bytes

__device__ __forceinline__ void rec_issue(uint32_t sbase, int s,
                                          const __half* pre, int chBase,
                                          int tid) {
    const uint32_t st = sbase + (s % RNS) * RSTG;
#pragma unroll
    for (int j = 0; j < 2; j++) {
        const int c = tid + j * 128;     // 256 chunks: 16 rows x 16 chunks
        const int row = c >> 4, col = c & 15;
        cp_async16(st + row * 256 + col * 16,
                   pre + (size_t)(s * RTC + row) * BH + chBase + col * 8);
    }
    cp_commit();
}

__global__ __launch_bounds__(128)
void rec_h2h_kernel(const __half* __restrict__ pre,
                    __half* __restrict__ out,
                    const float* __restrict__ h_init,
                    const float* __restrict__ u,
                    float* __restrict__ h_final) {
    __shared__ __align__(16) char sbuf[RSM];
    const uint32_t sbase = smem_u32(sbuf);
    const int tid = threadIdx.x;
    const int chBase = blockIdx.x * 128;
    const int ch = chBase + tid;
    const float uu = u[ch & (H_SZ - 1)];
    float h = h_init[ch];

#pragma unroll
    for (int s = 0; s < RNS - 1; s++) rec_issue(sbase, s, pre, chBase, tid);

    for (int s = 0; s < T_LEN / RTC; s++) {
        cp_wait6();                    // group s complete (7+s issued, wait<=6)
        __syncthreads();
        const __half* hb = (const __half*)(sbuf + (s % RNS) * RSTG);
#pragma unroll
        for (int j = 0; j < RTC; j++) {
            float cur = __half2float(hb[j * 128 + tid]);
            h = fmaxf(fmaf(uu, h, cur), 0.f);
            out[(size_t)(s * RTC + j) * BH + ch] = __float2half_rn(h);
        }
        if (s + RNS - 1 < T_LEN / RTC)
            rec_issue(sbase, s + RNS - 1, pre, chBase, tid);
        else
            cp_commit();               // empty group: tail correctness
    }
    h_final[ch] = h;
}

__global__ __launch_bounds__(128)
void rec_h2f_kernel(const __half* __restrict__ pre,
                    float* __restrict__ out,
                    const float* __restrict__ h_init,
                    const float* __restrict__ u,
                    float* __restrict__ h_final) {
    __shared__ __align__(16) char sbuf[RSM];
    const uint32_t sbase = smem_u32(sbuf);
    const int tid = threadIdx.x;
    const int chBase = blockIdx.x * 128;
    const int ch = chBase + tid;
    const float uu = u[ch & (H_SZ - 1)];
    float h = h_init[ch];

#pragma unroll
    for (int s = 0; s < RNS - 1; s++) rec_issue(sbase, s, pre, chBase, tid);

    for (int s = 0; s < T_LEN / RTC; s++) {
        cp_wait6();
        __syncthreads();
        const __half* hb = (const __half*)(sbuf + (s % RNS) * RSTG);
#pragma unroll
        for (int j = 0; j < RTC; j++) {
            float cur = __half2float(hb[j * 128 + tid]);
            h = fmaxf(fmaf(uu, h, cur), 0.f);
            out[(size_t)(s * RTC + j) * BH + ch] = h;
        }
        if (s + RNS - 1 < T_LEN / RTC)
            rec_issue(sbase, s + RNS - 1, pre, chBase, tid);
        else
            cp_commit();               // empty group: tail correctness
    }
    h_final[ch] = h;
}

// ---------------------------------------------------------------------------
// Launch
//   inputs: x, hidden, fc_w, fc_b, w0, b0, u0, w1, b1, u1
//   output: [ out1 (T*B*H) | hn (2*B*H) ]
// ---------------------------------------------------------------------------
extern "C" void kernel_launch(void* const* d_in, const int* in_sizes, int n_in,
                              void* d_out, int out_size) {
    const float* x      = (const float*)d_in[0];
    const float* hidden = (const float*)d_in[1];
    const float* fc_w   = (const float*)d_in[2];
    const float* fc_b   = (const float*)d_in[3];
    const float* w0     = (const float*)d_in[4];
    const float* b0     = (const float*)d_in[5];
    const float* u0     = (const float*)d_in[6];
    const float* w1     = (const float*)d_in[7];
    const float* b1     = (const float*)d_in[8];
    const float* u1     = (const float*)d_in[9];
    float* out = (float*)d_out;

    float *bc;
    __half *Wch, *w1h, *xh, *o0h, *pre;
    cudaGetSymbolAddress((void**)&bc,  g_bc);
    cudaGetSymbolAddress((void**)&pre, g_pre);
    cudaGetSymbolAddress((void**)&Wch, g_Wch);
    cudaGetSymbolAddress((void**)&w1h, g_w1h);
    cudaGetSymbolAddress((void**)&xh,  g_xh);
    cudaGetSymbolAddress((void**)&o0h, g_o0h);

    cudaFuncSetAttribute(gemm_hmma_kernel,
                         cudaFuncAttributeMaxDynamicSharedMemorySize, GSMEM);

    // 1) fuse fc into layer-0 weights -> fp16 directly; bias; convert w1
    fuse_weights_kernel<<<dim3(8, 8), 256>>>(w0, fc_w);
    fuse_bias_kernel<<<2, 256>>>(w0, fc_b, b0);
    convert_kernel<<<(D_SZ * D_SZ / 4 + 255) / 256, 256>>>(w1, w1h, D_SZ * D_SZ / 4);

    // 2) convert x to fp16
    convert_kernel<<<(TBH / 4 + 255) / 256, 256>>>(x, xh, TBH / 4);

    // 3) pre0 = x @ Wch^T + bc   (fp16 out)
    gemm_hmma_kernel<<<T_LEN * B_SZ / 128 * 4, 256, GSMEM>>>(xh, Wch, bc, pre);

    // 4) layer-0 recurrence -> fp16 out0, h0_final
    rec_h2h_kernel<<<BH / 128, 128>>>(pre, o0h, hidden, u0, out + TBH);

    // 5) pre1 = out0 @ w1h^T + b1   (fp16 out)
    gemm_hmma_kernel<<<T_LEN * B_SZ / 128 * 4, 256, GSMEM>>>(o0h, w1h, b1, pre);

    // 6) layer-1 recurrence -> d_out, h1_final
    rec_h2f_kernel<<<BH / 128, 128>>>(pre, out, hidden + BH, u1, out + TBH + BH);
}